// round 14
// baseline (speedup 1.0000x reference)
#include <cuda_runtime.h>
#include <cstdint>

// Problem constants
#define BB 32
#define SS 1024
#define EE 768
#define HH 64
#define LL 2
#define MM (BB * SS)
#define NQKV (3 * EE)        // 2304

typedef unsigned short u16;

// ---------------------------------------------------------------------------
// Scratch (static device allocations)
// ---------------------------------------------------------------------------
__device__ u16  g_hid_h[(size_t)MM * EE], g_hid_l[(size_t)MM * EE];
__device__ u16  g_wqkv_h[(size_t)NQKV * EE], g_wqkv_l[(size_t)NQKV * EE];
__device__ float g_bqkv[NQKV];
__device__ u16  g_qkv_h[(size_t)MM * NQKV], g_qkv_l[(size_t)MM * NQKV];
__device__ u16  g_p_h[(size_t)BB * SS * SS], g_p_l[(size_t)BB * SS * SS];
__device__ float g_s[(size_t)BB * SS * SS];
__device__ float g_a[(size_t)MM * EE];
__device__ float g_w1t[EE * HH];

// ---------------------------------------------------------------------------
// helpers
// ---------------------------------------------------------------------------
__device__ __forceinline__ uint32_t smem_u32(const void* p) {
    return (uint32_t)__cvta_generic_to_shared(p);
}
__device__ __forceinline__ void ldm4(uint32_t* r, uint32_t addr) {
    asm volatile("ldmatrix.sync.aligned.m8n8.x4.shared.b16 {%0,%1,%2,%3}, [%4];"
                 : "=r"(r[0]), "=r"(r[1]), "=r"(r[2]), "=r"(r[3]) : "r"(addr));
}
__device__ __forceinline__ void ldm4t(uint32_t* r, uint32_t addr) {
    asm volatile("ldmatrix.sync.aligned.m8n8.x4.trans.shared.b16 {%0,%1,%2,%3}, [%4];"
                 : "=r"(r[0]), "=r"(r[1]), "=r"(r[2]), "=r"(r[3]) : "r"(addr));
}
__device__ __forceinline__ void mma16816(float* d, const uint32_t* a,
                                         uint32_t b0, uint32_t b1) {
    asm volatile(
        "mma.sync.aligned.m16n8k16.row.col.f32.bf16.bf16.f32 "
        "{%0,%1,%2,%3},{%4,%5,%6,%7},{%8,%9},{%0,%1,%2,%3};"
        : "+f"(d[0]), "+f"(d[1]), "+f"(d[2]), "+f"(d[3])
        : "r"(a[0]), "r"(a[1]), "r"(a[2]), "r"(a[3]), "r"(b0), "r"(b1));
}
__device__ __forceinline__ void cpasync16(uint32_t smem, const void* g) {
    asm volatile("cp.async.cg.shared.global [%0], [%1], 16;"
                 :: "r"(smem), "l"(g) : "memory");
}
#define CP_COMMIT() asm volatile("cp.async.commit_group;" ::: "memory")
#define CP_WAIT(n)  asm volatile("cp.async.wait_group %0;" :: "n"(n) : "memory")

// hardware f32 pair -> bf16x2 (hi) + residual bf16x2 (lo); lo half = first arg
__device__ __forceinline__ uint32_t pack2(float a, float b) {
    uint32_t r;
    asm("cvt.rn.bf16x2.f32 %0, %1, %2;" : "=r"(r) : "f"(b), "f"(a));
    return r;
}
__device__ __forceinline__ void cvt_hl(float a, float b, uint32_t& h, uint32_t& l) {
    h = pack2(a, b);
    float ha = __uint_as_float(h << 16);
    float hb = __uint_as_float(h & 0xffff0000u);
    l = pack2(a - ha, b - hb);
}

// ---------------------------------------------------------------------------
// One-time f32 -> (hi, lo) bf16 split, vectorized (hidden)
// ---------------------------------------------------------------------------
__global__ void split_f32(const float4* __restrict__ x, uint2* __restrict__ h,
                          uint2* __restrict__ l, int n4)
{
    for (int i = blockIdx.x * blockDim.x + threadIdx.x; i < n4;
         i += gridDim.x * blockDim.x) {
        float4 f = x[i];
        uint2 hh, ll;
        cvt_hl(f.x, f.y, hh.x, ll.x);
        cvt_hl(f.z, f.w, hh.y, ll.y);
        h[i] = hh; l[i] = ll;
    }
}

// ---------------------------------------------------------------------------
// Fused weight prep: split Wq|Wk|Wv, concat biases, transpose W1.
// ---------------------------------------------------------------------------
__global__ void prep_weights(
    const float4* __restrict__ Wq, const float4* __restrict__ Wk,
    const float4* __restrict__ Wv,
    const float* __restrict__ bq, const float* __restrict__ bk,
    const float* __restrict__ bv, const float* __restrict__ W1,
    uint2* __restrict__ wh, uint2* __restrict__ wl,
    float* __restrict__ bqkv, float* __restrict__ w1t)
{
    const int stride = gridDim.x * blockDim.x;
    const int gid = blockIdx.x * blockDim.x + threadIdx.x;
    const int W4 = EE * EE / 4;
    for (int i = gid; i < 3 * W4; i += stride) {
        const int which = i / W4, r = i - which * W4;
        const float4 f = (which == 0 ? Wq : which == 1 ? Wk : Wv)[r];
        uint2 hh, ll;
        cvt_hl(f.x, f.y, hh.x, ll.x);
        cvt_hl(f.z, f.w, hh.y, ll.y);
        wh[(size_t)which * W4 + r] = hh;
        wl[(size_t)which * W4 + r] = ll;
    }
    for (int i = gid; i < EE; i += stride) {
        bqkv[i] = bq[i]; bqkv[i + EE] = bk[i]; bqkv[i + 2 * EE] = bv[i];
    }
    for (int i = gid; i < HH * EE; i += stride)
        w1t[(i % EE) * HH + (i / EE)] = W1[i];
}

// ---------------------------------------------------------------------------
// Split-bf16 tensor-core GEMM: C[m,n] = sum_k A[m,k]*B(k,n) + bias[n]
// 512 threads = 16 warps (4x4), warp tile 32x64. cp.async gmem->smem.
// Fragment software pipeline: per k-step, ALL 12 ldmatrix issued upfront,
// then 96 MMAs globally term-major (no LDSM interleaved, RAW sep = 32).
//   BTRANS=false: B K-major [n][k];  BTRANS=true: B [k][n] (PV), ldmatrix.trans
//   SPLITOUT: epilogue emits hi/lo bf16 arrays instead of f32
// Block 128x256x32, double-buffered.
// ---------------------------------------------------------------------------
#define RSA 40     // A (and K-major B) smem row stride, u16
#define RSBT 264   // trans-B smem row stride, u16

template<bool BTRANS, bool CAUSAL, bool PVLIM, bool SPLITOUT>
__global__ __launch_bounds__(512, 1) void gemm_bf16(
    const u16* __restrict__ Agh, const u16* __restrict__ Agl,
    const u16* __restrict__ Bgh, const u16* __restrict__ Bgl,
    const float* __restrict__ bias,
    float* __restrict__ Cf, u16* __restrict__ Ch, u16* __restrict__ Cl,
    int K, int lda, int ldb, int ldc,
    long long sA, long long sB, long long sC)
{
    const int n0 = blockIdx.x * 256;
    const int m0 = blockIdx.y * 128;
    if (CAUSAL && n0 >= m0 + 128) return;

    Agh += (long long)blockIdx.z * sA; Agl += (long long)blockIdx.z * sA;
    Bgh += (long long)blockIdx.z * sB; Bgl += (long long)blockIdx.z * sB;
    if (SPLITOUT) {
        Ch += (long long)blockIdx.z * sC; Cl += (long long)blockIdx.z * sC;
    } else {
        Cf += (long long)blockIdx.z * sC;
    }

    int kend = PVLIM ? (m0 + 128) : K;
    const int ktiles = kend / 32;

    constexpr int ASZ = 128 * RSA;
    constexpr int BSZ = BTRANS ? 32 * RSBT : 256 * RSA;
    constexpr int OAh = 0, OAl = ASZ, OBh = 2 * ASZ, OBl = 2 * ASZ + BSZ;
    constexpr int STGU = 2 * ASZ + 2 * BSZ;

    extern __shared__ __align__(16) u16 sm[];
    const uint32_t smB = smem_u32(sm);

    const int tid  = threadIdx.x;
    const int lane = tid & 31;
    const int wid  = tid >> 5;
    const int wm   = wid >> 2;   // 0..3 (32 m-rows each)
    const int wn   = wid & 3;    // 0..3 (64 n-cols each)

    const int wmBase = m0 + wm * 32;
    const int wnBase = n0 + wn * 64;

    // cp.async staging
    const int a_row = tid >> 2, a_kc = (tid & 3) * 8;
    const uint32_t a_off = (uint32_t)(a_row * RSA + a_kc) * 2;

    auto issueT = [&](int k0, int s) {
        const uint32_t stB = smB + (uint32_t)s * (STGU * 2);
        cpasync16(stB + OAh * 2 + a_off, Agh + (size_t)(m0 + a_row) * lda + k0 + a_kc);
        cpasync16(stB + OAl * 2 + a_off, Agl + (size_t)(m0 + a_row) * lda + k0 + a_kc);
        if (!BTRANS) {
#pragma unroll
            for (int t = 0; t < 2; t++) {
                const int u = tid + t * 512;
                const int row = u >> 2, kc = (u & 3) * 8;
                const uint32_t off = (uint32_t)(row * RSA + kc) * 2;
                const size_t g = (size_t)(n0 + row) * ldb + k0 + kc;
                cpasync16(stB + OBh * 2 + off, Bgh + g);
                cpasync16(stB + OBl * 2 + off, Bgl + g);
            }
        } else {
#pragma unroll
            for (int t = 0; t < 2; t++) {
                const int u = tid + t * 512;
                const int kr = u >> 5, nc = (u & 31) * 8;
                const uint32_t off = (uint32_t)(kr * RSBT + nc) * 2;
                const size_t g = (size_t)(k0 + kr) * ldb + n0 + nc;
                cpasync16(stB + OBh * 2 + off, Bgh + g);
                cpasync16(stB + OBl * 2 + off, Bgl + g);
            }
        }
    };

    // fragment addressing
    const int aRow  = wm * 32 + (lane & 7) + ((lane >> 3) & 1) * 8;
    const int aColS = ((lane >> 4) & 1) * 8;
    const int bRow  = wn * 64 + (lane & 7) + ((lane >> 4) & 1) * 8;
    const int bColS = ((lane >> 3) & 1) * 8;
    const int btK = (lane & 7) + ((lane >> 3) & 1) * 8;
    const int btN = wn * 64 + ((lane >> 4) & 1) * 8;

    float acc[2][8][4];
#pragma unroll
    for (int i = 0; i < 2; i++)
#pragma unroll
        for (int j = 0; j < 8; j++)
#pragma unroll
            for (int c = 0; c < 4; c++) acc[i][j][c] = 0.f;

    issueT(0, 0);
    CP_COMMIT();

    int s = 0;
    for (int kt = 0; kt < ktiles; kt++) {
        const bool more = (kt + 1 < ktiles);
        if (more) {
            issueT((kt + 1) * 32, s ^ 1);
            CP_COMMIT();
            CP_WAIT(1);
        } else {
            CP_WAIT(0);
        }
        __syncthreads();

        const uint32_t stB = smB + (uint32_t)s * (STGU * 2);
#pragma unroll
        for (int ks = 0; ks < 2; ks++) {
            // PV: this warp's P rows are all-zero for k > wmBase+31 -> skip.
            const bool wactive = !PVLIM || (kt * 32 + ks * 16 <= wmBase + 31);
            if (wactive) {
                // ---- all fragment loads upfront (12 x ldmatrix.x4) ----
                uint32_t ah[2][4], al[2][4], bh[4][4], bl[4][4];
#pragma unroll
                for (int mt = 0; mt < 2; mt++) {
                    uint32_t off = (uint32_t)(((aRow + mt * 16) * RSA) + ks * 16 + aColS) * 2;
                    ldm4(ah[mt], stB + OAh * 2 + off);
                    ldm4(al[mt], stB + OAl * 2 + off);
                }
#pragma unroll
                for (int np = 0; np < 4; np++) {
                    const bool np_active = !CAUSAL || (wnBase + np * 16 <= wmBase + 31);
                    if (!np_active) continue;
                    if (!BTRANS) {
                        uint32_t off = (uint32_t)(((bRow + np * 16) * RSA) + ks * 16 + bColS) * 2;
                        ldm4(bh[np], stB + OBh * 2 + off);
                        ldm4(bl[np], stB + OBl * 2 + off);
                    } else {
                        uint32_t off = (uint32_t)((ks * 16 + btK) * RSBT + btN + np * 16) * 2;
                        ldm4t(bh[np], stB + OBh * 2 + off);
                        ldm4t(bl[np], stB + OBl * 2 + off);
                    }
                }
                // ---- MMA phase: globally term-major, no LDSM interleave ----
#pragma unroll
                for (int np = 0; np < 4; np++) {
                    if (CAUSAL && (wnBase + np * 16 > wmBase + 31)) continue;
#pragma unroll
                    for (int h = 0; h < 2; h++)
#pragma unroll
                        for (int mt = 0; mt < 2; mt++)
                            if (!CAUSAL || (wnBase + (np * 2 + h) * 8 <= wmBase + mt * 16 + 15))
                                mma16816(acc[mt][np * 2 + h], ah[mt], bh[np][2 * h], bh[np][2 * h + 1]);
                }
#pragma unroll
                for (int np = 0; np < 4; np++) {
                    if (CAUSAL && (wnBase + np * 16 > wmBase + 31)) continue;
#pragma unroll
                    for (int h = 0; h < 2; h++)
#pragma unroll
                        for (int mt = 0; mt < 2; mt++)
                            if (!CAUSAL || (wnBase + (np * 2 + h) * 8 <= wmBase + mt * 16 + 15))
                                mma16816(acc[mt][np * 2 + h], ah[mt], bl[np][2 * h], bl[np][2 * h + 1]);
                }
#pragma unroll
                for (int np = 0; np < 4; np++) {
                    if (CAUSAL && (wnBase + np * 16 > wmBase + 31)) continue;
#pragma unroll
                    for (int h = 0; h < 2; h++)
#pragma unroll
                        for (int mt = 0; mt < 2; mt++)
                            if (!CAUSAL || (wnBase + (np * 2 + h) * 8 <= wmBase + mt * 16 + 15))
                                mma16816(acc[mt][np * 2 + h], al[mt], bh[np][2 * h], bh[np][2 * h + 1]);
                }
            }
        }
        __syncthreads();
        s ^= 1;
    }

    // epilogue
#pragma unroll
    for (int mt = 0; mt < 2; mt++) {
        const int m = wmBase + mt * 16 + (lane >> 2);
#pragma unroll
        for (int nt = 0; nt < 8; nt++) {
            const int n = wnBase + nt * 8 + (lane & 3) * 2;
            float b0 = 0.f, b1 = 0.f;
            if (bias) { b0 = bias[n]; b1 = bias[n + 1]; }
            if (!SPLITOUT) {
                float2 v0 = {acc[mt][nt][0] + b0, acc[mt][nt][1] + b1};
                float2 v1 = {acc[mt][nt][2] + b0, acc[mt][nt][3] + b1};
                // causal: softmax never reads above the diagonal -> skip stores
                if (!CAUSAL || n <= m)
                    *reinterpret_cast<float2*>(&Cf[(size_t)m * ldc + n]) = v0;
                if (!CAUSAL || n <= m + 8)
                    *reinterpret_cast<float2*>(&Cf[(size_t)(m + 8) * ldc + n]) = v1;
            } else {
                uint32_t h, l;
                cvt_hl(acc[mt][nt][0] + b0, acc[mt][nt][1] + b1, h, l);
                *reinterpret_cast<uint32_t*>(&Ch[(size_t)m * ldc + n]) = h;
                *reinterpret_cast<uint32_t*>(&Cl[(size_t)m * ldc + n]) = l;
                cvt_hl(acc[mt][nt][2] + b0, acc[mt][nt][3] + b1, h, l);
                *reinterpret_cast<uint32_t*>(&Ch[(size_t)(m + 8) * ldc + n]) = h;
                *reinterpret_cast<uint32_t*>(&Cl[(size_t)(m + 8) * ldc + n]) = l;
            }
        }
    }
}

#define SMEM_NT ((2 * (2 * 128 * RSA + 2 * 256 * RSA)) * 2)
#define SMEM_T  ((2 * (2 * 128 * RSA + 2 * 32 * RSBT)) * 2)

// ---------------------------------------------------------------------------
// Row-wise causal softmax -> split-bf16 P, trimmed to jmax = round128(i+1).
// ---------------------------------------------------------------------------
__global__ __launch_bounds__(256) void softmax_causal(
    const float* __restrict__ Smat, const float* __restrict__ amask,
    u16* __restrict__ Ph, u16* __restrict__ Pl)
{
    const int i = blockIdx.x;
    const int b = blockIdx.y;
    const int jmax = ((i >> 7) + 1) << 7;           // 128..1024
    const size_t rbase = ((size_t)b * SS + i) * SS;
    const float* row = Smat + rbase;
    const float* am = amask + (size_t)b * SS;
    const int tid = threadIdx.x;

    float vals[4];
    int cnt = 0;
    float mx = -1e30f;
    for (int j = tid * 2; j < jmax; j += 512) {
        float s0 = -10000.0f, s1 = -10000.0f;
        if (j <= i) {
            float2 f = *reinterpret_cast<const float2*>(&row[j]);
            s0 = f.x + (1.0f - am[j]) * -10000.0f;
            if (j + 1 <= i) s1 = f.y + (1.0f - am[j + 1]) * -10000.0f;
        }
        vals[cnt] = s0; vals[cnt + 1] = s1; cnt += 2;
        mx = fmaxf(mx, fmaxf(s0, s1));
    }

    __shared__ float red[8];
#pragma unroll
    for (int o = 16; o > 0; o >>= 1) mx = fmaxf(mx, __shfl_xor_sync(0xffffffffu, mx, o));
    if ((tid & 31) == 0) red[tid >> 5] = mx;
    __syncthreads();
    mx = red[0];
#pragma unroll
    for (int w = 1; w < 8; w++) mx = fmaxf(mx, red[w]);

    float sum = 0.f;
    for (int c = 0; c < cnt; c++) {
        vals[c] = __expf(vals[c] - mx);
        sum += vals[c];
    }
#pragma unroll
    for (int o = 16; o > 0; o >>= 1) sum += __shfl_xor_sync(0xffffffffu, sum, o);
    __syncthreads();
    if ((tid & 31) == 0) red[tid >> 5] = sum;
    __syncthreads();
    sum = 0.f;
#pragma unroll
    for (int w = 0; w < 8; w++) sum += red[w];

    const float inv = 1.0f / sum;
    int c = 0;
    for (int j = tid * 2; j < jmax; j += 512) {
        uint32_t h, l;
        cvt_hl(vals[c] * inv, vals[c + 1] * inv, h, l);
        c += 2;
        *reinterpret_cast<uint32_t*>(&Ph[rbase + j]) = h;
        *reinterpret_cast<uint32_t*>(&Pl[rbase + j]) = l;
    }
}

// ---------------------------------------------------------------------------
// Fused MLP head: out = relu(X @ W1^T + b1) @ W2^T + b2
// ---------------------------------------------------------------------------
__global__ __launch_bounds__(256) void mlp_kernel(
    const float* __restrict__ X, const float* __restrict__ W1t,
    const float* __restrict__ b1, const float* __restrict__ W2,
    const float* __restrict__ b2, float* __restrict__ out)
{
    __shared__ float xs[4][EE];
    __shared__ float hs[4][HH];
    const int row0 = blockIdx.x * 4;
    const int tid = threadIdx.x;

    for (int v = tid; v < 4 * EE; v += 256)
        xs[v / EE][v % EE] = X[(size_t)(row0 + v / EE) * EE + (v % EE)];
    __syncthreads();

    const int c  = tid & 63;
    const int rr = tid >> 6;
    float a0 = 0.f, a1 = 0.f, a2 = 0.f, a3 = 0.f;
#pragma unroll 4
    for (int e = 0; e < EE; e += 4) {
        a0 += xs[rr][e + 0] * W1t[(e + 0) * HH + c];
        a1 += xs[rr][e + 1] * W1t[(e + 1) * HH + c];
        a2 += xs[rr][e + 2] * W1t[(e + 2) * HH + c];
        a3 += xs[rr][e + 3] * W1t[(e + 3) * HH + c];
    }
    float acc = b1[c] + ((a0 + a1) + (a2 + a3));
    hs[rr][c] = fmaxf(acc, 0.f);
    __syncthreads();

    if (tid < 4 * LL) {
        int r2 = tid >> 1;
        int l  = tid & 1;
        float s = b2[l];
#pragma unroll
        for (int h = 0; h < HH; h++) s += hs[r2][h] * W2[l * HH + h];
        out[(size_t)(row0 + r2) * LL + l] = s;
    }
}

// ---------------------------------------------------------------------------
extern "C" void kernel_launch(void* const* d_in, const int* in_sizes, int n_in,
                              void* d_out, int out_size)
{
    const float* hidden = (const float*)d_in[0];
    const float* amask  = (const float*)d_in[1];
    const float* Wk = (const float*)d_in[2];
    const float* bk = (const float*)d_in[3];
    const float* Wq = (const float*)d_in[4];
    const float* bq = (const float*)d_in[5];
    const float* Wv = (const float*)d_in[6];
    const float* bv = (const float*)d_in[7];
    const float* W1 = (const float*)d_in[8];
    const float* b1 = (const float*)d_in[9];
    const float* W2 = (const float*)d_in[10];
    const float* b2 = (const float*)d_in[11];
    float* out = (float*)d_out;

    u16 *hid_h, *hid_l, *wqkv_h, *wqkv_l, *qkv_h, *qkv_l, *p_h, *p_l;
    float *bqkv, *sbuf, *abuf, *w1t;
    cudaGetSymbolAddress((void**)&hid_h, g_hid_h); cudaGetSymbolAddress((void**)&hid_l, g_hid_l);
    cudaGetSymbolAddress((void**)&wqkv_h, g_wqkv_h); cudaGetSymbolAddress((void**)&wqkv_l, g_wqkv_l);
    cudaGetSymbolAddress((void**)&bqkv, g_bqkv);
    cudaGetSymbolAddress((void**)&qkv_h, g_qkv_h); cudaGetSymbolAddress((void**)&qkv_l, g_qkv_l);
    cudaGetSymbolAddress((void**)&p_h, g_p_h);     cudaGetSymbolAddress((void**)&p_l, g_p_l);
    cudaGetSymbolAddress((void**)&sbuf, g_s);
    cudaGetSymbolAddress((void**)&abuf, g_a);
    cudaGetSymbolAddress((void**)&w1t, g_w1t);

    cudaFuncSetAttribute((const void*)gemm_bf16<false, false, false, true>,
                         cudaFuncAttributeMaxDynamicSharedMemorySize, SMEM_NT);
    cudaFuncSetAttribute((const void*)gemm_bf16<false, true, false, false>,
                         cudaFuncAttributeMaxDynamicSharedMemorySize, SMEM_NT);
    cudaFuncSetAttribute((const void*)gemm_bf16<true, false, true, false>,
                         cudaFuncAttributeMaxDynamicSharedMemorySize, SMEM_T);

    const dim3 blk(256);
    const dim3 gblk(512);

    // Prep: hidden split + fused weight prep
    split_f32<<<2368, blk>>>((const float4*)hidden, (uint2*)hid_h, (uint2*)hid_l,
                             MM * EE / 4);
    prep_weights<<<1184, blk>>>((const float4*)Wq, (const float4*)Wk,
                                (const float4*)Wv, bq, bk, bv, W1,
                                (uint2*)wqkv_h, (uint2*)wqkv_l, bqkv, w1t);

    // Fused QKV projection: [M, 2304] = hidden @ [Wq|Wk|Wv]^T + bias, split out
    gemm_bf16<false, false, false, true><<<dim3(NQKV / 256, MM / 128, 1), gblk, SMEM_NT>>>(
        hid_h, hid_l, wqkv_h, wqkv_l, bqkv, nullptr, qkv_h, qkv_l,
        EE, EE, EE, NQKV, 0, 0, 0);

    // Scores: q = cols [0,768), k = cols [768,1536) of qkv (strided views)
    gemm_bf16<false, true, false, false><<<dim3(SS / 256, SS / 128, BB), gblk, SMEM_NT>>>(
        qkv_h, qkv_l, qkv_h + EE, qkv_l + EE, nullptr, sbuf, nullptr, nullptr,
        EE, NQKV, NQKV, SS,
        (long long)SS * NQKV, (long long)SS * NQKV, (long long)SS * SS);

    // Softmax -> split-bf16 P (trimmed to round128(i+1))
    softmax_causal<<<dim3(SS, BB), blk>>>(sbuf, amask, p_h, p_l);

    // PV: A = P (K-major), B = V = cols [1536,2304) of qkv, [s][e] via trans
    gemm_bf16<true, false, true, false><<<dim3(EE / 256, SS / 128, BB), gblk, SMEM_T>>>(
        p_h, p_l, qkv_h + 2 * EE, qkv_l + 2 * EE, nullptr, abuf, nullptr, nullptr,
        SS, SS, NQKV, EE,
        (long long)SS * SS, (long long)SS * NQKV, (long long)SS * EE);

    // Fused MLP head -> out [B*S, 2]
    mlp_kernel<<<MM / 4, blk>>>(abuf, w1t, b1, W2, b2, out);
}

// round 15
// speedup vs baseline: 1.1133x; 1.1133x over previous
#include <cuda_runtime.h>
#include <cstdint>

// Problem constants
#define BB 32
#define SS 1024
#define EE 768
#define HH 64
#define LL 2
#define MM (BB * SS)
#define NQKV (3 * EE)        // 2304

typedef unsigned short u16;

// ---------------------------------------------------------------------------
// Scratch (static device allocations)
// ---------------------------------------------------------------------------
__device__ u16  g_hid_h[(size_t)MM * EE], g_hid_l[(size_t)MM * EE];
__device__ u16  g_wqkv_h[(size_t)NQKV * EE], g_wqkv_l[(size_t)NQKV * EE];
__device__ float g_bqkv[NQKV];
__device__ u16  g_qkv_h[(size_t)MM * NQKV], g_qkv_l[(size_t)MM * NQKV];
__device__ u16  g_v16[(size_t)MM * EE];                 // V as single fp16 [s][e]
__device__ u16  g_p_h[(size_t)BB * SS * SS], g_p_l[(size_t)BB * SS * SS];  // P fp16 2-term
__device__ float g_s[(size_t)BB * SS * SS];
__device__ float g_a[(size_t)MM * EE];
__device__ float g_w1t[EE * HH];

// ---------------------------------------------------------------------------
// helpers
// ---------------------------------------------------------------------------
__device__ __forceinline__ uint32_t smem_u32(const void* p) {
    return (uint32_t)__cvta_generic_to_shared(p);
}
__device__ __forceinline__ void ldm4(uint32_t* r, uint32_t addr) {
    asm volatile("ldmatrix.sync.aligned.m8n8.x4.shared.b16 {%0,%1,%2,%3}, [%4];"
                 : "=r"(r[0]), "=r"(r[1]), "=r"(r[2]), "=r"(r[3]) : "r"(addr));
}
__device__ __forceinline__ void ldm4t(uint32_t* r, uint32_t addr) {
    asm volatile("ldmatrix.sync.aligned.m8n8.x4.trans.shared.b16 {%0,%1,%2,%3}, [%4];"
                 : "=r"(r[0]), "=r"(r[1]), "=r"(r[2]), "=r"(r[3]) : "r"(addr));
}
__device__ __forceinline__ void mma16816(float* d, const uint32_t* a,
                                         uint32_t b0, uint32_t b1) {
    asm volatile(
        "mma.sync.aligned.m16n8k16.row.col.f32.bf16.bf16.f32 "
        "{%0,%1,%2,%3},{%4,%5,%6,%7},{%8,%9},{%0,%1,%2,%3};"
        : "+f"(d[0]), "+f"(d[1]), "+f"(d[2]), "+f"(d[3])
        : "r"(a[0]), "r"(a[1]), "r"(a[2]), "r"(a[3]), "r"(b0), "r"(b1));
}
__device__ __forceinline__ void mma16816h(float* d, const uint32_t* a,
                                          uint32_t b0, uint32_t b1) {
    asm volatile(
        "mma.sync.aligned.m16n8k16.row.col.f32.f16.f16.f32 "
        "{%0,%1,%2,%3},{%4,%5,%6,%7},{%8,%9},{%0,%1,%2,%3};"
        : "+f"(d[0]), "+f"(d[1]), "+f"(d[2]), "+f"(d[3])
        : "r"(a[0]), "r"(a[1]), "r"(a[2]), "r"(a[3]), "r"(b0), "r"(b1));
}

// ---- bf16 split (hi, lo) ----
__device__ __forceinline__ uint32_t pack2(float a, float b) {   // lo=a, hi=b
    uint32_t r;
    asm("cvt.rn.bf16x2.f32 %0, %1, %2;" : "=r"(r) : "f"(b), "f"(a));
    return r;
}
__device__ __forceinline__ void cvt_hl(float a, float b, uint32_t& h, uint32_t& l) {
    h = pack2(a, b);
    float ha = __uint_as_float(h << 16);
    float hb = __uint_as_float(h & 0xffff0000u);
    l = pack2(a - ha, b - hb);
}

// ---- fp16 pack / split ----
__device__ __forceinline__ uint32_t pack2f(float a, float b) {  // lo=a, hi=b
    uint32_t r;
    asm("cvt.rn.f16x2.f32 %0, %1, %2;" : "=r"(r) : "f"(b), "f"(a));
    return r;
}
__device__ __forceinline__ void cvt_hl_f16(float a, float b, uint32_t& h, uint32_t& l) {
    h = pack2f(a, b);
    float ha, hb;
    asm("{ .reg .f16 x,y;\n\t mov.b32 {x,y}, %2;\n\t"
        "cvt.f32.f16 %0, x;\n\t cvt.f32.f16 %1, y; }"
        : "=f"(ha), "=f"(hb) : "r"(h));
    l = pack2f(a - ha, b - hb);
}

// ---------------------------------------------------------------------------
// One-time f32 -> (hi, lo) bf16 split, vectorized (hidden)
// ---------------------------------------------------------------------------
__global__ void split_f32(const float4* __restrict__ x, uint2* __restrict__ h,
                          uint2* __restrict__ l, int n4)
{
    for (int i = blockIdx.x * blockDim.x + threadIdx.x; i < n4;
         i += gridDim.x * blockDim.x) {
        float4 f = x[i];
        uint2 hh, ll;
        cvt_hl(f.x, f.y, hh.x, ll.x);
        cvt_hl(f.z, f.w, hh.y, ll.y);
        h[i] = hh; l[i] = ll;
    }
}

// ---------------------------------------------------------------------------
// Fused weight prep: split Wq|Wk|Wv, concat biases, transpose W1.
// ---------------------------------------------------------------------------
__global__ void prep_weights(
    const float4* __restrict__ Wq, const float4* __restrict__ Wk,
    const float4* __restrict__ Wv,
    const float* __restrict__ bq, const float* __restrict__ bk,
    const float* __restrict__ bv, const float* __restrict__ W1,
    uint2* __restrict__ wh, uint2* __restrict__ wl,
    float* __restrict__ bqkv, float* __restrict__ w1t)
{
    const int stride = gridDim.x * blockDim.x;
    const int gid = blockIdx.x * blockDim.x + threadIdx.x;
    const int W4 = EE * EE / 4;
    for (int i = gid; i < 3 * W4; i += stride) {
        const int which = i / W4, r = i - which * W4;
        const float4 f = (which == 0 ? Wq : which == 1 ? Wk : Wv)[r];
        uint2 hh, ll;
        cvt_hl(f.x, f.y, hh.x, ll.x);
        cvt_hl(f.z, f.w, hh.y, ll.y);
        wh[(size_t)which * W4 + r] = hh;
        wl[(size_t)which * W4 + r] = ll;
    }
    for (int i = gid; i < EE; i += stride) {
        bqkv[i] = bq[i]; bqkv[i + EE] = bk[i]; bqkv[i + 2 * EE] = bv[i];
    }
    for (int i = gid; i < HH * EE; i += stride)
        w1t[(i % EE) * HH + (i / EE)] = W1[i];
}

// ---------------------------------------------------------------------------
// Split-bf16 tensor-core GEMM (QKV + scores): C = A @ B^T + bias
// R8 structure: 256 threads, 8 warps (2x4), warp 64x64, register staging,
// double-buffered, term-major MMA nest, causal skip + epilogue store-skip.
//   SPLITOUT: q/k columns (n<1536) -> bf16 hi/lo; V columns (n0>=1536) ->
//             single fp16 into Vf[s][e]   (V precision is enough for PV).
// ---------------------------------------------------------------------------
#define RSA 40     // smem row stride, u16
#define RSBT 264   // PV trans-B smem row stride, u16

template<bool CAUSAL, bool SPLITOUT>
__global__ __launch_bounds__(256, 1) void gemm_bf16(
    const u16* __restrict__ Agh, const u16* __restrict__ Agl,
    const u16* __restrict__ Bgh, const u16* __restrict__ Bgl,
    const float* __restrict__ bias,
    float* __restrict__ Cf, u16* __restrict__ Ch, u16* __restrict__ Cl,
    u16* __restrict__ Vf,
    int K, int lda, int ldb, int ldc,
    long long sA, long long sB, long long sC)
{
    const int n0 = blockIdx.x * 256;
    const int m0 = blockIdx.y * 128;
    if (CAUSAL && n0 >= m0 + 128) return;

    Agh += (long long)blockIdx.z * sA; Agl += (long long)blockIdx.z * sA;
    Bgh += (long long)blockIdx.z * sB; Bgl += (long long)blockIdx.z * sB;
    if (!SPLITOUT) Cf += (long long)blockIdx.z * sC;

    const int ktiles = K / 32;
    const bool vmode = SPLITOUT && (n0 >= 1536);

    constexpr int ASZ = 128 * RSA;
    constexpr int BSZ = 256 * RSA;
    constexpr int OAh = 0, OAl = ASZ, OBh = 2 * ASZ, OBl = 2 * ASZ + BSZ;
    constexpr int STGU = 2 * ASZ + 2 * BSZ;

    extern __shared__ __align__(16) u16 sm[];

    const int tid  = threadIdx.x;
    const int lane = tid & 31;
    const int wid  = tid >> 5;
    const int wm   = wid >> 2;   // 0..1
    const int wn   = wid & 3;    // 0..3

    const int wmBase = m0 + wm * 64;
    const int wnBase = n0 + wn * 64;

    uint4 rah[2], ral[2], rbh[4], rbl[4];

    auto loadT = [&](int k0) {
#pragma unroll
        for (int t = 0; t < 2; t++) {
            const int v = tid + t * 256;
            const size_t g = (size_t)(m0 + (v >> 2)) * lda + k0 + (v & 3) * 8;
            rah[t] = *reinterpret_cast<const uint4*>(Agh + g);
            ral[t] = *reinterpret_cast<const uint4*>(Agl + g);
        }
#pragma unroll
        for (int t = 0; t < 4; t++) {
            const int v = tid + t * 256;
            const size_t g = (size_t)(n0 + (v >> 2)) * ldb + k0 + (v & 3) * 8;
            rbh[t] = *reinterpret_cast<const uint4*>(Bgh + g);
            rbl[t] = *reinterpret_cast<const uint4*>(Bgl + g);
        }
    };

    auto storeT = [&](int s) {
        u16* base = sm + s * STGU;
#pragma unroll
        for (int t = 0; t < 2; t++) {
            const int v = tid + t * 256;
            const int off = (v >> 2) * RSA + (v & 3) * 8;
            *reinterpret_cast<uint4*>(base + OAh + off) = rah[t];
            *reinterpret_cast<uint4*>(base + OAl + off) = ral[t];
        }
#pragma unroll
        for (int t = 0; t < 4; t++) {
            const int v = tid + t * 256;
            const int off = (v >> 2) * RSA + (v & 3) * 8;
            *reinterpret_cast<uint4*>(base + OBh + off) = rbh[t];
            *reinterpret_cast<uint4*>(base + OBl + off) = rbl[t];
        }
    };

    const uint32_t smB = smem_u32(sm);
    const int aRow  = wm * 64 + (lane & 7) + ((lane >> 3) & 1) * 8;
    const int aColS = ((lane >> 4) & 1) * 8;
    const int bRow  = wn * 64 + (lane & 7) + ((lane >> 4) & 1) * 8;
    const int bColS = ((lane >> 3) & 1) * 8;

    float acc[4][8][4];
#pragma unroll
    for (int i = 0; i < 4; i++)
#pragma unroll
        for (int j = 0; j < 8; j++)
#pragma unroll
            for (int c = 0; c < 4; c++) acc[i][j][c] = 0.f;

    loadT(0);
    storeT(0);
    __syncthreads();

    int s = 0;
    for (int kt = 0; kt < ktiles; kt++) {
        const bool more = (kt + 1 < ktiles);
        if (more) loadT((kt + 1) * 32);

        const uint32_t stB = smB + (uint32_t)s * (STGU * 2);
#pragma unroll
        for (int ks = 0; ks < 2; ks++) {
            uint32_t ah[4][4], al[4][4];
#pragma unroll
            for (int mt = 0; mt < 4; mt++) {
                uint32_t off = (uint32_t)(((aRow + mt * 16) * RSA) + ks * 16 + aColS) * 2;
                ldm4(ah[mt], stB + OAh * 2 + off);
                ldm4(al[mt], stB + OAl * 2 + off);
            }
#pragma unroll
            for (int np = 0; np < 4; np++) {
                const bool np_active = !CAUSAL || (wnBase + np * 16 <= wmBase + 63);
                if (!np_active) continue;
                uint32_t bh[4], bl[4];
                uint32_t off = (uint32_t)(((bRow + np * 16) * RSA) + ks * 16 + bColS) * 2;
                ldm4(bh, stB + OBh * 2 + off);
                ldm4(bl, stB + OBl * 2 + off);
                // term-major: break accumulator RAW chains
#pragma unroll
                for (int h = 0; h < 2; h++)
#pragma unroll
                    for (int mt = 0; mt < 4; mt++)
                        if (!CAUSAL || (wnBase + (np * 2 + h) * 8 <= wmBase + mt * 16 + 15))
                            mma16816(acc[mt][np * 2 + h], ah[mt], bh[2 * h], bh[2 * h + 1]);
#pragma unroll
                for (int h = 0; h < 2; h++)
#pragma unroll
                    for (int mt = 0; mt < 4; mt++)
                        if (!CAUSAL || (wnBase + (np * 2 + h) * 8 <= wmBase + mt * 16 + 15))
                            mma16816(acc[mt][np * 2 + h], ah[mt], bl[2 * h], bl[2 * h + 1]);
#pragma unroll
                for (int h = 0; h < 2; h++)
#pragma unroll
                    for (int mt = 0; mt < 4; mt++)
                        if (!CAUSAL || (wnBase + (np * 2 + h) * 8 <= wmBase + mt * 16 + 15))
                            mma16816(acc[mt][np * 2 + h], al[mt], bh[2 * h], bh[2 * h + 1]);
            }
            if (ks == 0 && more) storeT(s ^ 1);
        }
        __syncthreads();
        s ^= 1;
    }

    // epilogue
#pragma unroll
    for (int mt = 0; mt < 4; mt++) {
        const int m = m0 + wm * 64 + mt * 16 + (lane >> 2);
#pragma unroll
        for (int nt = 0; nt < 8; nt++) {
            const int n = n0 + wn * 64 + nt * 8 + (lane & 3) * 2;
            float b0 = 0.f, b1 = 0.f;
            if (bias) { b0 = bias[n]; b1 = bias[n + 1]; }
            const float x0 = acc[mt][nt][0] + b0, x1 = acc[mt][nt][1] + b1;
            const float x2 = acc[mt][nt][2] + b0, x3 = acc[mt][nt][3] + b1;
            if (!SPLITOUT) {
                float2 v0 = {x0, x1}, v1 = {x2, x3};
                if (!CAUSAL || n <= m)
                    *reinterpret_cast<float2*>(&Cf[(size_t)m * ldc + n]) = v0;
                if (!CAUSAL || n <= m + 8)
                    *reinterpret_cast<float2*>(&Cf[(size_t)(m + 8) * ldc + n]) = v1;
            } else if (!vmode) {
                uint32_t h, l;
                cvt_hl(x0, x1, h, l);
                *reinterpret_cast<uint32_t*>(&Ch[(size_t)m * ldc + n]) = h;
                *reinterpret_cast<uint32_t*>(&Cl[(size_t)m * ldc + n]) = l;
                cvt_hl(x2, x3, h, l);
                *reinterpret_cast<uint32_t*>(&Ch[(size_t)(m + 8) * ldc + n]) = h;
                *reinterpret_cast<uint32_t*>(&Cl[(size_t)(m + 8) * ldc + n]) = l;
            } else {
                const int nv = n - 1536;
                *reinterpret_cast<uint32_t*>(&Vf[(size_t)m * EE + nv]) = pack2f(x0, x1);
                *reinterpret_cast<uint32_t*>(&Vf[(size_t)(m + 8) * EE + nv]) = pack2f(x2, x3);
            }
        }
    }
}

// ---------------------------------------------------------------------------
// PV GEMM (fp16, 2 MMAs per k-step): a = P @ V,  P = Ph + Pl (fp16 2-term),
// V single fp16 [s][e] (ldm4t). 256 threads, warp 64x64, causal k-limit +
// per-warp zero-row skip. Block 128x256x32, double-buffered.
// ---------------------------------------------------------------------------
__global__ __launch_bounds__(256, 1) void gemm_pv(
    const u16* __restrict__ Pgh, const u16* __restrict__ Pgl,
    const u16* __restrict__ Vg, float* __restrict__ Cf)
{
    const int n0 = blockIdx.x * 256;
    const int m0 = blockIdx.y * 128;

    Pgh += (long long)blockIdx.z * SS * SS;
    Pgl += (long long)blockIdx.z * SS * SS;
    Vg  += (long long)blockIdx.z * SS * EE;
    Cf  += (long long)blockIdx.z * SS * EE;

    const int ktiles = (m0 + 128) / 32;

    constexpr int ASZ = 128 * RSA;
    constexpr int BSZ = 32 * RSBT;
    constexpr int OAh = 0, OAl = ASZ, OBv = 2 * ASZ;
    constexpr int STGU = 2 * ASZ + BSZ;

    extern __shared__ __align__(16) u16 sm[];
    const uint32_t smB = smem_u32(sm);

    const int tid  = threadIdx.x;
    const int lane = tid & 31;
    const int wid  = tid >> 5;
    const int wm   = wid >> 2;
    const int wn   = wid & 3;

    const int wmBase = m0 + wm * 64;

    uint4 rah[2], ral[2], rbv[4];

    auto loadT = [&](int k0) {
#pragma unroll
        for (int t = 0; t < 2; t++) {
            const int v = tid + t * 256;
            const size_t g = (size_t)(m0 + (v >> 2)) * SS + k0 + (v & 3) * 8;
            rah[t] = *reinterpret_cast<const uint4*>(Pgh + g);
            ral[t] = *reinterpret_cast<const uint4*>(Pgl + g);
        }
#pragma unroll
        for (int t = 0; t < 4; t++) {
            const int u = tid + t * 256;          // 0..1023
            const size_t g = (size_t)(k0 + (u >> 5)) * EE + n0 + (u & 31) * 8;
            rbv[t] = *reinterpret_cast<const uint4*>(Vg + g);
        }
    };

    auto storeT = [&](int s) {
        u16* base = sm + s * STGU;
#pragma unroll
        for (int t = 0; t < 2; t++) {
            const int v = tid + t * 256;
            const int off = (v >> 2) * RSA + (v & 3) * 8;
            *reinterpret_cast<uint4*>(base + OAh + off) = rah[t];
            *reinterpret_cast<uint4*>(base + OAl + off) = ral[t];
        }
#pragma unroll
        for (int t = 0; t < 4; t++) {
            const int u = tid + t * 256;
            const int off = (u >> 5) * RSBT + (u & 31) * 8;
            *reinterpret_cast<uint4*>(base + OBv + off) = rbv[t];
        }
    };

    const int aRow  = wm * 64 + (lane & 7) + ((lane >> 3) & 1) * 8;
    const int aColS = ((lane >> 4) & 1) * 8;
    const int btK = (lane & 7) + ((lane >> 3) & 1) * 8;
    const int btN = wn * 64 + ((lane >> 4) & 1) * 8;

    float acc[4][8][4];
#pragma unroll
    for (int i = 0; i < 4; i++)
#pragma unroll
        for (int j = 0; j < 8; j++)
#pragma unroll
            for (int c = 0; c < 4; c++) acc[i][j][c] = 0.f;

    loadT(0);
    storeT(0);
    __syncthreads();

    int s = 0;
    for (int kt = 0; kt < ktiles; kt++) {
        const bool more = (kt + 1 < ktiles);
        if (more) loadT((kt + 1) * 32);

        const uint32_t stB = smB + (uint32_t)s * (STGU * 2);
#pragma unroll
        for (int ks = 0; ks < 2; ks++) {
            // this warp's P rows are exactly zero for k > wmBase+63 -> skip
            const bool wactive = (kt * 32 + ks * 16 <= wmBase + 63);
            if (wactive) {
                uint32_t ah[4][4], al[4][4];
#pragma unroll
                for (int mt = 0; mt < 4; mt++) {
                    uint32_t off = (uint32_t)(((aRow + mt * 16) * RSA) + ks * 16 + aColS) * 2;
                    ldm4(ah[mt], stB + OAh * 2 + off);
                    ldm4(al[mt], stB + OAl * 2 + off);
                }
#pragma unroll
                for (int np = 0; np < 4; np++) {
                    uint32_t bv[4];
                    uint32_t off = (uint32_t)((ks * 16 + btK) * RSBT + btN + np * 16) * 2;
                    ldm4t(bv, stB + OBv * 2 + off);
#pragma unroll
                    for (int h = 0; h < 2; h++)
#pragma unroll
                        for (int mt = 0; mt < 4; mt++)
                            mma16816h(acc[mt][np * 2 + h], ah[mt], bv[2 * h], bv[2 * h + 1]);
#pragma unroll
                    for (int h = 0; h < 2; h++)
#pragma unroll
                        for (int mt = 0; mt < 4; mt++)
                            mma16816h(acc[mt][np * 2 + h], al[mt], bv[2 * h], bv[2 * h + 1]);
                }
            }
            if (ks == 0 && more) storeT(s ^ 1);
        }
        __syncthreads();
        s ^= 1;
    }

    // epilogue (f32)
#pragma unroll
    for (int mt = 0; mt < 4; mt++) {
        const int m = m0 + wm * 64 + mt * 16 + (lane >> 2);
#pragma unroll
        for (int nt = 0; nt < 8; nt++) {
            const int n = n0 + wn * 64 + nt * 8 + (lane & 3) * 2;
            float2 v0 = {acc[mt][nt][0], acc[mt][nt][1]};
            float2 v1 = {acc[mt][nt][2], acc[mt][nt][3]};
            *reinterpret_cast<float2*>(&Cf[(size_t)m * EE + n]) = v0;
            *reinterpret_cast<float2*>(&Cf[(size_t)(m + 8) * EE + n]) = v1;
        }
    }
}

#define SMEM_NT ((2 * (2 * 128 * RSA + 2 * 256 * RSA)) * 2)
#define SMEM_PV ((2 * (2 * 128 * RSA + 32 * RSBT)) * 2)

// ---------------------------------------------------------------------------
// Row-wise causal softmax -> fp16 2-term P, trimmed to jmax = round128(i+1).
// ---------------------------------------------------------------------------
__global__ __launch_bounds__(256) void softmax_causal(
    const float* __restrict__ Smat, const float* __restrict__ amask,
    u16* __restrict__ Ph, u16* __restrict__ Pl)
{
    const int i = blockIdx.x;
    const int b = blockIdx.y;
    const int jmax = ((i >> 7) + 1) << 7;           // 128..1024
    const size_t rbase = ((size_t)b * SS + i) * SS;
    const float* row = Smat + rbase;
    const float* am = amask + (size_t)b * SS;
    const int tid = threadIdx.x;

    float vals[4];
    int cnt = 0;
    float mx = -1e30f;
    for (int j = tid * 2; j < jmax; j += 512) {
        float s0 = -10000.0f, s1 = -10000.0f;
        if (j <= i) {
            float2 f = *reinterpret_cast<const float2*>(&row[j]);
            s0 = f.x + (1.0f - am[j]) * -10000.0f;
            if (j + 1 <= i) s1 = f.y + (1.0f - am[j + 1]) * -10000.0f;
        }
        vals[cnt] = s0; vals[cnt + 1] = s1; cnt += 2;
        mx = fmaxf(mx, fmaxf(s0, s1));
    }

    __shared__ float red[8];
#pragma unroll
    for (int o = 16; o > 0; o >>= 1) mx = fmaxf(mx, __shfl_xor_sync(0xffffffffu, mx, o));
    if ((tid & 31) == 0) red[tid >> 5] = mx;
    __syncthreads();
    mx = red[0];
#pragma unroll
    for (int w = 1; w < 8; w++) mx = fmaxf(mx, red[w]);

    float sum = 0.f;
    for (int c = 0; c < cnt; c++) {
        vals[c] = __expf(vals[c] - mx);
        sum += vals[c];
    }
#pragma unroll
    for (int o = 16; o > 0; o >>= 1) sum += __shfl_xor_sync(0xffffffffu, sum, o);
    __syncthreads();
    if ((tid & 31) == 0) red[tid >> 5] = sum;
    __syncthreads();
    sum = 0.f;
#pragma unroll
    for (int w = 0; w < 8; w++) sum += red[w];

    const float inv = 1.0f / sum;
    int c = 0;
    for (int j = tid * 2; j < jmax; j += 512) {
        uint32_t h, l;
        cvt_hl_f16(vals[c] * inv, vals[c + 1] * inv, h, l);
        c += 2;
        *reinterpret_cast<uint32_t*>(&Ph[rbase + j]) = h;
        *reinterpret_cast<uint32_t*>(&Pl[rbase + j]) = l;
    }
}

// ---------------------------------------------------------------------------
// Fused MLP head: out = relu(X @ W1^T + b1) @ W2^T + b2
// ---------------------------------------------------------------------------
__global__ __launch_bounds__(256) void mlp_kernel(
    const float* __restrict__ X, const float* __restrict__ W1t,
    const float* __restrict__ b1, const float* __restrict__ W2,
    const float* __restrict__ b2, float* __restrict__ out)
{
    __shared__ float xs[4][EE];
    __shared__ float hs[4][HH];
    const int row0 = blockIdx.x * 4;
    const int tid = threadIdx.x;

    for (int v = tid; v < 4 * EE; v += 256)
        xs[v / EE][v % EE] = X[(size_t)(row0 + v / EE) * EE + (v % EE)];
    __syncthreads();

    const int c  = tid & 63;
    const int rr = tid >> 6;
    float a0 = 0.f, a1 = 0.f, a2 = 0.f, a3 = 0.f;
#pragma unroll 4
    for (int e = 0; e < EE; e += 4) {
        a0 += xs[rr][e + 0] * W1t[(e + 0) * HH + c];
        a1 += xs[rr][e + 1] * W1t[(e + 1) * HH + c];
        a2 += xs[rr][e + 2] * W1t[(e + 2) * HH + c];
        a3 += xs[rr][e + 3] * W1t[(e + 3) * HH + c];
    }
    float acc = b1[c] + ((a0 + a1) + (a2 + a3));
    hs[rr][c] = fmaxf(acc, 0.f);
    __syncthreads();

    if (tid < 4 * LL) {
        int r2 = tid >> 1;
        int l  = tid & 1;
        float s = b2[l];
#pragma unroll
        for (int h = 0; h < HH; h++) s += hs[r2][h] * W2[l * HH + h];
        out[(size_t)(row0 + r2) * LL + l] = s;
    }
}

// ---------------------------------------------------------------------------
extern "C" void kernel_launch(void* const* d_in, const int* in_sizes, int n_in,
                              void* d_out, int out_size)
{
    const float* hidden = (const float*)d_in[0];
    const float* amask  = (const float*)d_in[1];
    const float* Wk = (const float*)d_in[2];
    const float* bk = (const float*)d_in[3];
    const float* Wq = (const float*)d_in[4];
    const float* bq = (const float*)d_in[5];
    const float* Wv = (const float*)d_in[6];
    const float* bv = (const float*)d_in[7];
    const float* W1 = (const float*)d_in[8];
    const float* b1 = (const float*)d_in[9];
    const float* W2 = (const float*)d_in[10];
    const float* b2 = (const float*)d_in[11];
    float* out = (float*)d_out;

    u16 *hid_h, *hid_l, *wqkv_h, *wqkv_l, *qkv_h, *qkv_l, *v16, *p_h, *p_l;
    float *bqkv, *sbuf, *abuf, *w1t;
    cudaGetSymbolAddress((void**)&hid_h, g_hid_h); cudaGetSymbolAddress((void**)&hid_l, g_hid_l);
    cudaGetSymbolAddress((void**)&wqkv_h, g_wqkv_h); cudaGetSymbolAddress((void**)&wqkv_l, g_wqkv_l);
    cudaGetSymbolAddress((void**)&bqkv, g_bqkv);
    cudaGetSymbolAddress((void**)&qkv_h, g_qkv_h); cudaGetSymbolAddress((void**)&qkv_l, g_qkv_l);
    cudaGetSymbolAddress((void**)&v16, g_v16);
    cudaGetSymbolAddress((void**)&p_h, g_p_h);     cudaGetSymbolAddress((void**)&p_l, g_p_l);
    cudaGetSymbolAddress((void**)&sbuf, g_s);
    cudaGetSymbolAddress((void**)&abuf, g_a);
    cudaGetSymbolAddress((void**)&w1t, g_w1t);

    cudaFuncSetAttribute((const void*)gemm_bf16<false, true>,
                         cudaFuncAttributeMaxDynamicSharedMemorySize, SMEM_NT);
    cudaFuncSetAttribute((const void*)gemm_bf16<true, false>,
                         cudaFuncAttributeMaxDynamicSharedMemorySize, SMEM_NT);
    cudaFuncSetAttribute((const void*)gemm_pv,
                         cudaFuncAttributeMaxDynamicSharedMemorySize, SMEM_PV);

    const dim3 blk(256);

    // Prep: hidden split + fused weight prep
    split_f32<<<2368, blk>>>((const float4*)hidden, (uint2*)hid_h, (uint2*)hid_l,
                             MM * EE / 4);
    prep_weights<<<1184, blk>>>((const float4*)Wq, (const float4*)Wk,
                                (const float4*)Wv, bq, bk, bv, W1,
                                (uint2*)wqkv_h, (uint2*)wqkv_l, bqkv, w1t);

    // Fused QKV projection: q/k -> bf16 hi/lo, V -> single fp16
    gemm_bf16<false, true><<<dim3(NQKV / 256, MM / 128, 1), blk, SMEM_NT>>>(
        hid_h, hid_l, wqkv_h, wqkv_l, bqkv, nullptr, qkv_h, qkv_l, v16,
        EE, EE, EE, NQKV, 0, 0, 0);

    // Scores: q = cols [0,768), k = cols [768,1536) of qkv
    gemm_bf16<true, false><<<dim3(SS / 256, SS / 128, BB), blk, SMEM_NT>>>(
        qkv_h, qkv_l, qkv_h + EE, qkv_l + EE, nullptr, sbuf, nullptr, nullptr,
        nullptr, EE, NQKV, NQKV, SS,
        (long long)SS * NQKV, (long long)SS * NQKV, (long long)SS * SS);

    // Softmax -> fp16 2-term P (trimmed)
    softmax_causal<<<dim3(SS, BB), blk>>>(sbuf, amask, p_h, p_l);

    // PV: fp16, 2 MMAs per k-step
    gemm_pv<<<dim3(EE / 256, SS / 128, BB), blk, SMEM_PV>>>(p_h, p_l, v16, abuf);

    // Fused MLP head -> out [B*S, 2]
    mlp_kernel<<<MM / 4, blk>>>(abuf, w1t, b1, W2, b2, out);
}

// round 16
// speedup vs baseline: 1.1438x; 1.0274x over previous
#include <cuda_runtime.h>
#include <cstdint>

// Problem constants
#define BB 32
#define SS 1024
#define EE 768
#define HH 64
#define LL 2
#define MM (BB * SS)
#define NQKV (3 * EE)        // 2304

typedef unsigned short u16;

// ---------------------------------------------------------------------------
// Scratch (static device allocations)
// ---------------------------------------------------------------------------
__device__ u16  g_hid_h[(size_t)MM * EE], g_hid_l[(size_t)MM * EE];
__device__ u16  g_wqkv_h[(size_t)NQKV * EE], g_wqkv_l[(size_t)NQKV * EE];
__device__ float g_bqkv[NQKV];
__device__ u16  g_qkv_h[(size_t)MM * NQKV], g_qkv_l[(size_t)MM * NQKV];
__device__ u16  g_v16[(size_t)MM * EE];                 // V as single fp16 [s][e]
__device__ u16  g_p16[(size_t)BB * SS * SS];            // P as single fp16
__device__ float g_s[(size_t)BB * SS * SS];
__device__ float g_a[(size_t)MM * EE];
__device__ float g_w1t[EE * HH];

// ---------------------------------------------------------------------------
// helpers
// ---------------------------------------------------------------------------
__device__ __forceinline__ uint32_t smem_u32(const void* p) {
    return (uint32_t)__cvta_generic_to_shared(p);
}
__device__ __forceinline__ void ldm4(uint32_t* r, uint32_t addr) {
    asm volatile("ldmatrix.sync.aligned.m8n8.x4.shared.b16 {%0,%1,%2,%3}, [%4];"
                 : "=r"(r[0]), "=r"(r[1]), "=r"(r[2]), "=r"(r[3]) : "r"(addr));
}
__device__ __forceinline__ void ldm4t(uint32_t* r, uint32_t addr) {
    asm volatile("ldmatrix.sync.aligned.m8n8.x4.trans.shared.b16 {%0,%1,%2,%3}, [%4];"
                 : "=r"(r[0]), "=r"(r[1]), "=r"(r[2]), "=r"(r[3]) : "r"(addr));
}
__device__ __forceinline__ void mma16816(float* d, const uint32_t* a,
                                         uint32_t b0, uint32_t b1) {
    asm volatile(
        "mma.sync.aligned.m16n8k16.row.col.f32.bf16.bf16.f32 "
        "{%0,%1,%2,%3},{%4,%5,%6,%7},{%8,%9},{%0,%1,%2,%3};"
        : "+f"(d[0]), "+f"(d[1]), "+f"(d[2]), "+f"(d[3])
        : "r"(a[0]), "r"(a[1]), "r"(a[2]), "r"(a[3]), "r"(b0), "r"(b1));
}
__device__ __forceinline__ void mma16816h(float* d, const uint32_t* a,
                                          uint32_t b0, uint32_t b1) {
    asm volatile(
        "mma.sync.aligned.m16n8k16.row.col.f32.f16.f16.f32 "
        "{%0,%1,%2,%3},{%4,%5,%6,%7},{%8,%9},{%0,%1,%2,%3};"
        : "+f"(d[0]), "+f"(d[1]), "+f"(d[2]), "+f"(d[3])
        : "r"(a[0]), "r"(a[1]), "r"(a[2]), "r"(a[3]), "r"(b0), "r"(b1));
}

// ---- bf16 split (hi, lo) ----
__device__ __forceinline__ uint32_t pack2(float a, float b) {   // lo=a, hi=b
    uint32_t r;
    asm("cvt.rn.bf16x2.f32 %0, %1, %2;" : "=r"(r) : "f"(b), "f"(a));
    return r;
}
__device__ __forceinline__ void cvt_hl(float a, float b, uint32_t& h, uint32_t& l) {
    h = pack2(a, b);
    float ha = __uint_as_float(h << 16);
    float hb = __uint_as_float(h & 0xffff0000u);
    l = pack2(a - ha, b - hb);
}

// ---- fp16 pack ----
__device__ __forceinline__ uint32_t pack2f(float a, float b) {  // lo=a, hi=b
    uint32_t r;
    asm("cvt.rn.f16x2.f32 %0, %1, %2;" : "=r"(r) : "f"(b), "f"(a));
    return r;
}

// ---------------------------------------------------------------------------
// One-time f32 -> (hi, lo) bf16 split, vectorized (hidden)
// ---------------------------------------------------------------------------
__global__ void split_f32(const float4* __restrict__ x, uint2* __restrict__ h,
                          uint2* __restrict__ l, int n4)
{
    for (int i = blockIdx.x * blockDim.x + threadIdx.x; i < n4;
         i += gridDim.x * blockDim.x) {
        float4 f = x[i];
        uint2 hh, ll;
        cvt_hl(f.x, f.y, hh.x, ll.x);
        cvt_hl(f.z, f.w, hh.y, ll.y);
        h[i] = hh; l[i] = ll;
    }
}

// ---------------------------------------------------------------------------
// Fused weight prep: split Wq|Wk|Wv, concat biases, transpose W1.
// ---------------------------------------------------------------------------
__global__ void prep_weights(
    const float4* __restrict__ Wq, const float4* __restrict__ Wk,
    const float4* __restrict__ Wv,
    const float* __restrict__ bq, const float* __restrict__ bk,
    const float* __restrict__ bv, const float* __restrict__ W1,
    uint2* __restrict__ wh, uint2* __restrict__ wl,
    float* __restrict__ bqkv, float* __restrict__ w1t)
{
    const int stride = gridDim.x * blockDim.x;
    const int gid = blockIdx.x * blockDim.x + threadIdx.x;
    const int W4 = EE * EE / 4;
    for (int i = gid; i < 3 * W4; i += stride) {
        const int which = i / W4, r = i - which * W4;
        const float4 f = (which == 0 ? Wq : which == 1 ? Wk : Wv)[r];
        uint2 hh, ll;
        cvt_hl(f.x, f.y, hh.x, ll.x);
        cvt_hl(f.z, f.w, hh.y, ll.y);
        wh[(size_t)which * W4 + r] = hh;
        wl[(size_t)which * W4 + r] = ll;
    }
    for (int i = gid; i < EE; i += stride) {
        bqkv[i] = bq[i]; bqkv[i + EE] = bk[i]; bqkv[i + 2 * EE] = bv[i];
    }
    for (int i = gid; i < HH * EE; i += stride)
        w1t[(i % EE) * HH + (i / EE)] = W1[i];
}

// ---------------------------------------------------------------------------
// Split-bf16 tensor-core GEMM (QKV + scores): C = A @ B^T + bias
// 256 threads, 8 warps (2x4), warp 64x64, register staging, double-buffered,
// term-major MMA nest, causal skip + epilogue store-skip.
//   SPLITOUT: q/k columns (n<1536) -> bf16 hi/lo; V columns (n0>=1536) ->
//             single fp16 into Vf[s][e].
// ---------------------------------------------------------------------------
#define RSA 40     // smem row stride, u16
#define RSBT 264   // PV trans-B smem row stride, u16

template<bool CAUSAL, bool SPLITOUT>
__global__ __launch_bounds__(256, 1) void gemm_bf16(
    const u16* __restrict__ Agh, const u16* __restrict__ Agl,
    const u16* __restrict__ Bgh, const u16* __restrict__ Bgl,
    const float* __restrict__ bias,
    float* __restrict__ Cf, u16* __restrict__ Ch, u16* __restrict__ Cl,
    u16* __restrict__ Vf,
    int K, int lda, int ldb, int ldc,
    long long sA, long long sB, long long sC)
{
    const int n0 = blockIdx.x * 256;
    const int m0 = blockIdx.y * 128;
    if (CAUSAL && n0 >= m0 + 128) return;

    Agh += (long long)blockIdx.z * sA; Agl += (long long)blockIdx.z * sA;
    Bgh += (long long)blockIdx.z * sB; Bgl += (long long)blockIdx.z * sB;
    if (!SPLITOUT) Cf += (long long)blockIdx.z * sC;

    const int ktiles = K / 32;
    const bool vmode = SPLITOUT && (n0 >= 1536);

    constexpr int ASZ = 128 * RSA;
    constexpr int BSZ = 256 * RSA;
    constexpr int OAh = 0, OAl = ASZ, OBh = 2 * ASZ, OBl = 2 * ASZ + BSZ;
    constexpr int STGU = 2 * ASZ + 2 * BSZ;

    extern __shared__ __align__(16) u16 sm[];

    const int tid  = threadIdx.x;
    const int lane = tid & 31;
    const int wid  = tid >> 5;
    const int wm   = wid >> 2;   // 0..1
    const int wn   = wid & 3;    // 0..3

    const int wmBase = m0 + wm * 64;
    const int wnBase = n0 + wn * 64;

    uint4 rah[2], ral[2], rbh[4], rbl[4];

    auto loadT = [&](int k0) {
#pragma unroll
        for (int t = 0; t < 2; t++) {
            const int v = tid + t * 256;
            const size_t g = (size_t)(m0 + (v >> 2)) * lda + k0 + (v & 3) * 8;
            rah[t] = *reinterpret_cast<const uint4*>(Agh + g);
            ral[t] = *reinterpret_cast<const uint4*>(Agl + g);
        }
#pragma unroll
        for (int t = 0; t < 4; t++) {
            const int v = tid + t * 256;
            const size_t g = (size_t)(n0 + (v >> 2)) * ldb + k0 + (v & 3) * 8;
            rbh[t] = *reinterpret_cast<const uint4*>(Bgh + g);
            rbl[t] = *reinterpret_cast<const uint4*>(Bgl + g);
        }
    };

    auto storeT = [&](int s) {
        u16* base = sm + s * STGU;
#pragma unroll
        for (int t = 0; t < 2; t++) {
            const int v = tid + t * 256;
            const int off = (v >> 2) * RSA + (v & 3) * 8;
            *reinterpret_cast<uint4*>(base + OAh + off) = rah[t];
            *reinterpret_cast<uint4*>(base + OAl + off) = ral[t];
        }
#pragma unroll
        for (int t = 0; t < 4; t++) {
            const int v = tid + t * 256;
            const int off = (v >> 2) * RSA + (v & 3) * 8;
            *reinterpret_cast<uint4*>(base + OBh + off) = rbh[t];
            *reinterpret_cast<uint4*>(base + OBl + off) = rbl[t];
        }
    };

    const uint32_t smB = smem_u32(sm);
    const int aRow  = wm * 64 + (lane & 7) + ((lane >> 3) & 1) * 8;
    const int aColS = ((lane >> 4) & 1) * 8;
    const int bRow  = wn * 64 + (lane & 7) + ((lane >> 4) & 1) * 8;
    const int bColS = ((lane >> 3) & 1) * 8;

    float acc[4][8][4];
#pragma unroll
    for (int i = 0; i < 4; i++)
#pragma unroll
        for (int j = 0; j < 8; j++)
#pragma unroll
            for (int c = 0; c < 4; c++) acc[i][j][c] = 0.f;

    loadT(0);
    storeT(0);
    __syncthreads();

    int s = 0;
    for (int kt = 0; kt < ktiles; kt++) {
        const bool more = (kt + 1 < ktiles);
        if (more) loadT((kt + 1) * 32);

        const uint32_t stB = smB + (uint32_t)s * (STGU * 2);
#pragma unroll
        for (int ks = 0; ks < 2; ks++) {
            uint32_t ah[4][4], al[4][4];
#pragma unroll
            for (int mt = 0; mt < 4; mt++) {
                uint32_t off = (uint32_t)(((aRow + mt * 16) * RSA) + ks * 16 + aColS) * 2;
                ldm4(ah[mt], stB + OAh * 2 + off);
                ldm4(al[mt], stB + OAl * 2 + off);
            }
#pragma unroll
            for (int np = 0; np < 4; np++) {
                const bool np_active = !CAUSAL || (wnBase + np * 16 <= wmBase + 63);
                if (!np_active) continue;
                uint32_t bh[4], bl[4];
                uint32_t off = (uint32_t)(((bRow + np * 16) * RSA) + ks * 16 + bColS) * 2;
                ldm4(bh, stB + OBh * 2 + off);
                ldm4(bl, stB + OBl * 2 + off);
                // term-major: break accumulator RAW chains
#pragma unroll
                for (int h = 0; h < 2; h++)
#pragma unroll
                    for (int mt = 0; mt < 4; mt++)
                        if (!CAUSAL || (wnBase + (np * 2 + h) * 8 <= wmBase + mt * 16 + 15))
                            mma16816(acc[mt][np * 2 + h], ah[mt], bh[2 * h], bh[2 * h + 1]);
#pragma unroll
                for (int h = 0; h < 2; h++)
#pragma unroll
                    for (int mt = 0; mt < 4; mt++)
                        if (!CAUSAL || (wnBase + (np * 2 + h) * 8 <= wmBase + mt * 16 + 15))
                            mma16816(acc[mt][np * 2 + h], ah[mt], bl[2 * h], bl[2 * h + 1]);
#pragma unroll
                for (int h = 0; h < 2; h++)
#pragma unroll
                    for (int mt = 0; mt < 4; mt++)
                        if (!CAUSAL || (wnBase + (np * 2 + h) * 8 <= wmBase + mt * 16 + 15))
                            mma16816(acc[mt][np * 2 + h], al[mt], bh[2 * h], bh[2 * h + 1]);
            }
            if (ks == 0 && more) storeT(s ^ 1);
        }
        __syncthreads();
        s ^= 1;
    }

    // epilogue
#pragma unroll
    for (int mt = 0; mt < 4; mt++) {
        const int m = m0 + wm * 64 + mt * 16 + (lane >> 2);
#pragma unroll
        for (int nt = 0; nt < 8; nt++) {
            const int n = n0 + wn * 64 + nt * 8 + (lane & 3) * 2;
            float b0 = 0.f, b1 = 0.f;
            if (bias) { b0 = bias[n]; b1 = bias[n + 1]; }
            const float x0 = acc[mt][nt][0] + b0, x1 = acc[mt][nt][1] + b1;
            const float x2 = acc[mt][nt][2] + b0, x3 = acc[mt][nt][3] + b1;
            if (!SPLITOUT) {
                float2 v0 = {x0, x1}, v1 = {x2, x3};
                if (!CAUSAL || n <= m)
                    *reinterpret_cast<float2*>(&Cf[(size_t)m * ldc + n]) = v0;
                if (!CAUSAL || n <= m + 8)
                    *reinterpret_cast<float2*>(&Cf[(size_t)(m + 8) * ldc + n]) = v1;
            } else if (!vmode) {
                uint32_t h, l;
                cvt_hl(x0, x1, h, l);
                *reinterpret_cast<uint32_t*>(&Ch[(size_t)m * ldc + n]) = h;
                *reinterpret_cast<uint32_t*>(&Cl[(size_t)m * ldc + n]) = l;
                cvt_hl(x2, x3, h, l);
                *reinterpret_cast<uint32_t*>(&Ch[(size_t)(m + 8) * ldc + n]) = h;
                *reinterpret_cast<uint32_t*>(&Cl[(size_t)(m + 8) * ldc + n]) = l;
            } else {
                const int nv = n - 1536;
                *reinterpret_cast<uint32_t*>(&Vf[(size_t)m * EE + nv]) = pack2f(x0, x1);
                *reinterpret_cast<uint32_t*>(&Vf[(size_t)(m + 8) * EE + nv]) = pack2f(x2, x3);
            }
        }
    }
}

// ---------------------------------------------------------------------------
// PV GEMM (fp16, 1 MMA per k-step): a = P @ V, P single fp16, V single fp16
// [s][e] (ldm4t). 256 threads, warp 64x64, causal k-limit + per-warp
// zero-row skip. Block 128x256x32, double-buffered.
// ---------------------------------------------------------------------------
__global__ __launch_bounds__(256, 1) void gemm_pv(
    const u16* __restrict__ Pg, const u16* __restrict__ Vg,
    float* __restrict__ Cf)
{
    const int n0 = blockIdx.x * 256;
    const int m0 = blockIdx.y * 128;

    Pg += (long long)blockIdx.z * SS * SS;
    Vg += (long long)blockIdx.z * SS * EE;
    Cf += (long long)blockIdx.z * SS * EE;

    const int ktiles = (m0 + 128) / 32;

    constexpr int ASZ = 128 * RSA;
    constexpr int BSZ = 32 * RSBT;
    constexpr int OAp = 0, OBv = ASZ;
    constexpr int STGU = ASZ + BSZ;

    extern __shared__ __align__(16) u16 sm[];
    const uint32_t smB = smem_u32(sm);

    const int tid  = threadIdx.x;
    const int lane = tid & 31;
    const int wid  = tid >> 5;
    const int wm   = wid >> 2;
    const int wn   = wid & 3;

    const int wmBase = m0 + wm * 64;

    uint4 rap[2], rbv[4];

    auto loadT = [&](int k0) {
#pragma unroll
        for (int t = 0; t < 2; t++) {
            const int v = tid + t * 256;
            rap[t] = *reinterpret_cast<const uint4*>(
                Pg + (size_t)(m0 + (v >> 2)) * SS + k0 + (v & 3) * 8);
        }
#pragma unroll
        for (int t = 0; t < 4; t++) {
            const int u = tid + t * 256;          // 0..1023
            rbv[t] = *reinterpret_cast<const uint4*>(
                Vg + (size_t)(k0 + (u >> 5)) * EE + n0 + (u & 31) * 8);
        }
    };

    auto storeT = [&](int s) {
        u16* base = sm + s * STGU;
#pragma unroll
        for (int t = 0; t < 2; t++) {
            const int v = tid + t * 256;
            const int off = (v >> 2) * RSA + (v & 3) * 8;
            *reinterpret_cast<uint4*>(base + OAp + off) = rap[t];
        }
#pragma unroll
        for (int t = 0; t < 4; t++) {
            const int u = tid + t * 256;
            const int off = (u >> 5) * RSBT + (u & 31) * 8;
            *reinterpret_cast<uint4*>(base + OBv + off) = rbv[t];
        }
    };

    const int aRow  = wm * 64 + (lane & 7) + ((lane >> 3) & 1) * 8;
    const int aColS = ((lane >> 4) & 1) * 8;
    const int btK = (lane & 7) + ((lane >> 3) & 1) * 8;
    const int btN = wn * 64 + ((lane >> 4) & 1) * 8;

    float acc[4][8][4];
#pragma unroll
    for (int i = 0; i < 4; i++)
#pragma unroll
        for (int j = 0; j < 8; j++)
#pragma unroll
            for (int c = 0; c < 4; c++) acc[i][j][c] = 0.f;

    loadT(0);
    storeT(0);
    __syncthreads();

    int s = 0;
    for (int kt = 0; kt < ktiles; kt++) {
        const bool more = (kt + 1 < ktiles);
        if (more) loadT((kt + 1) * 32);

        const uint32_t stB = smB + (uint32_t)s * (STGU * 2);
#pragma unroll
        for (int ks = 0; ks < 2; ks++) {
            // this warp's P rows are exactly zero for k > wmBase+63 -> skip
            const bool wactive = (kt * 32 + ks * 16 <= wmBase + 63);
            if (wactive) {
                uint32_t ap[4][4];
#pragma unroll
                for (int mt = 0; mt < 4; mt++) {
                    uint32_t off = (uint32_t)(((aRow + mt * 16) * RSA) + ks * 16 + aColS) * 2;
                    ldm4(ap[mt], stB + OAp * 2 + off);
                }
#pragma unroll
                for (int np = 0; np < 4; np++) {
                    uint32_t bv[4];
                    uint32_t off = (uint32_t)((ks * 16 + btK) * RSBT + btN + np * 16) * 2;
                    ldm4t(bv, stB + OBv * 2 + off);
#pragma unroll
                    for (int h = 0; h < 2; h++)
#pragma unroll
                        for (int mt = 0; mt < 4; mt++)
                            mma16816h(acc[mt][np * 2 + h], ap[mt], bv[2 * h], bv[2 * h + 1]);
                }
            }
            if (ks == 0 && more) storeT(s ^ 1);
        }
        __syncthreads();
        s ^= 1;
    }

    // epilogue (f32)
#pragma unroll
    for (int mt = 0; mt < 4; mt++) {
        const int m = m0 + wm * 64 + mt * 16 + (lane >> 2);
#pragma unroll
        for (int nt = 0; nt < 8; nt++) {
            const int n = n0 + wn * 64 + nt * 8 + (lane & 3) * 2;
            float2 v0 = {acc[mt][nt][0], acc[mt][nt][1]};
            float2 v1 = {acc[mt][nt][2], acc[mt][nt][3]};
            *reinterpret_cast<float2*>(&Cf[(size_t)m * EE + n]) = v0;
            *reinterpret_cast<float2*>(&Cf[(size_t)(m + 8) * EE + n]) = v1;
        }
    }
}

#define SMEM_NT ((2 * (2 * 128 * RSA + 2 * 256 * RSA)) * 2)
#define SMEM_PV ((2 * (128 * RSA + 32 * RSBT)) * 2)

// ---------------------------------------------------------------------------
// Row-wise causal softmax -> single fp16 P, trimmed to jmax = round128(i+1).
// ---------------------------------------------------------------------------
__global__ __launch_bounds__(256) void softmax_causal(
    const float* __restrict__ Smat, const float* __restrict__ amask,
    u16* __restrict__ Ph)
{
    const int i = blockIdx.x;
    const int b = blockIdx.y;
    const int jmax = ((i >> 7) + 1) << 7;           // 128..1024
    const size_t rbase = ((size_t)b * SS + i) * SS;
    const float* row = Smat + rbase;
    const float* am = amask + (size_t)b * SS;
    const int tid = threadIdx.x;

    float vals[4];
    int cnt = 0;
    float mx = -1e30f;
    for (int j = tid * 2; j < jmax; j += 512) {
        float s0 = -10000.0f, s1 = -10000.0f;
        if (j <= i) {
            float2 f = *reinterpret_cast<const float2*>(&row[j]);
            s0 = f.x + (1.0f - am[j]) * -10000.0f;
            if (j + 1 <= i) s1 = f.y + (1.0f - am[j + 1]) * -10000.0f;
        }
        vals[cnt] = s0; vals[cnt + 1] = s1; cnt += 2;
        mx = fmaxf(mx, fmaxf(s0, s1));
    }

    __shared__ float red[8];
#pragma unroll
    for (int o = 16; o > 0; o >>= 1) mx = fmaxf(mx, __shfl_xor_sync(0xffffffffu, mx, o));
    if ((tid & 31) == 0) red[tid >> 5] = mx;
    __syncthreads();
    mx = red[0];
#pragma unroll
    for (int w = 1; w < 8; w++) mx = fmaxf(mx, red[w]);

    float sum = 0.f;
    for (int c = 0; c < cnt; c++) {
        vals[c] = __expf(vals[c] - mx);
        sum += vals[c];
    }
#pragma unroll
    for (int o = 16; o > 0; o >>= 1) sum += __shfl_xor_sync(0xffffffffu, sum, o);
    __syncthreads();
    if ((tid & 31) == 0) red[tid >> 5] = sum;
    __syncthreads();
    sum = 0.f;
#pragma unroll
    for (int w = 0; w < 8; w++) sum += red[w];

    const float inv = 1.0f / sum;
    int c = 0;
    for (int j = tid * 2; j < jmax; j += 512) {
        *reinterpret_cast<uint32_t*>(&Ph[rbase + j]) =
            pack2f(vals[c] * inv, vals[c + 1] * inv);
        c += 2;
    }
}

// ---------------------------------------------------------------------------
// Fused MLP head: out = relu(X @ W1^T + b1) @ W2^T + b2
// ---------------------------------------------------------------------------
__global__ __launch_bounds__(256) void mlp_kernel(
    const float* __restrict__ X, const float* __restrict__ W1t,
    const float* __restrict__ b1, const float* __restrict__ W2,
    const float* __restrict__ b2, float* __restrict__ out)
{
    __shared__ float xs[4][EE];
    __shared__ float hs[4][HH];
    const int row0 = blockIdx.x * 4;
    const int tid = threadIdx.x;

    for (int v = tid; v < 4 * EE; v += 256)
        xs[v / EE][v % EE] = X[(size_t)(row0 + v / EE) * EE + (v % EE)];
    __syncthreads();

    const int c  = tid & 63;
    const int rr = tid >> 6;
    float a0 = 0.f, a1 = 0.f, a2 = 0.f, a3 = 0.f;
#pragma unroll 4
    for (int e = 0; e < EE; e += 4) {
        a0 += xs[rr][e + 0] * W1t[(e + 0) * HH + c];
        a1 += xs[rr][e + 1] * W1t[(e + 1) * HH + c];
        a2 += xs[rr][e + 2] * W1t[(e + 2) * HH + c];
        a3 += xs[rr][e + 3] * W1t[(e + 3) * HH + c];
    }
    float acc = b1[c] + ((a0 + a1) + (a2 + a3));
    hs[rr][c] = fmaxf(acc, 0.f);
    __syncthreads();

    if (tid < 4 * LL) {
        int r2 = tid >> 1;
        int l  = tid & 1;
        float s = b2[l];
#pragma unroll
        for (int h = 0; h < HH; h++) s += hs[r2][h] * W2[l * HH + h];
        out[(size_t)(row0 + r2) * LL + l] = s;
    }
}

// ---------------------------------------------------------------------------
extern "C" void kernel_launch(void* const* d_in, const int* in_sizes, int n_in,
                              void* d_out, int out_size)
{
    const float* hidden = (const float*)d_in[0];
    const float* amask  = (const float*)d_in[1];
    const float* Wk = (const float*)d_in[2];
    const float* bk = (const float*)d_in[3];
    const float* Wq = (const float*)d_in[4];
    const float* bq = (const float*)d_in[5];
    const float* Wv = (const float*)d_in[6];
    const float* bv = (const float*)d_in[7];
    const float* W1 = (const float*)d_in[8];
    const float* b1 = (const float*)d_in[9];
    const float* W2 = (const float*)d_in[10];
    const float* b2 = (const float*)d_in[11];
    float* out = (float*)d_out;

    u16 *hid_h, *hid_l, *wqkv_h, *wqkv_l, *qkv_h, *qkv_l, *v16, *p16;
    float *bqkv, *sbuf, *abuf, *w1t;
    cudaGetSymbolAddress((void**)&hid_h, g_hid_h); cudaGetSymbolAddress((void**)&hid_l, g_hid_l);
    cudaGetSymbolAddress((void**)&wqkv_h, g_wqkv_h); cudaGetSymbolAddress((void**)&wqkv_l, g_wqkv_l);
    cudaGetSymbolAddress((void**)&bqkv, g_bqkv);
    cudaGetSymbolAddress((void**)&qkv_h, g_qkv_h); cudaGetSymbolAddress((void**)&qkv_l, g_qkv_l);
    cudaGetSymbolAddress((void**)&v16, g_v16);
    cudaGetSymbolAddress((void**)&p16, g_p16);
    cudaGetSymbolAddress((void**)&sbuf, g_s);
    cudaGetSymbolAddress((void**)&abuf, g_a);
    cudaGetSymbolAddress((void**)&w1t, g_w1t);

    cudaFuncSetAttribute((const void*)gemm_bf16<false, true>,
                         cudaFuncAttributeMaxDynamicSharedMemorySize, SMEM_NT);
    cudaFuncSetAttribute((const void*)gemm_bf16<true, false>,
                         cudaFuncAttributeMaxDynamicSharedMemorySize, SMEM_NT);
    cudaFuncSetAttribute((const void*)gemm_pv,
                         cudaFuncAttributeMaxDynamicSharedMemorySize, SMEM_PV);

    const dim3 blk(256);

    // Prep: hidden split + fused weight prep
    split_f32<<<2368, blk>>>((const float4*)hidden, (uint2*)hid_h, (uint2*)hid_l,
                             MM * EE / 4);
    prep_weights<<<1184, blk>>>((const float4*)Wq, (const float4*)Wk,
                                (const float4*)Wv, bq, bk, bv, W1,
                                (uint2*)wqkv_h, (uint2*)wqkv_l, bqkv, w1t);

    // Fused QKV projection: q/k -> bf16 hi/lo, V -> single fp16
    gemm_bf16<false, true><<<dim3(NQKV / 256, MM / 128, 1), blk, SMEM_NT>>>(
        hid_h, hid_l, wqkv_h, wqkv_l, bqkv, nullptr, qkv_h, qkv_l, v16,
        EE, EE, EE, NQKV, 0, 0, 0);

    // Scores: q = cols [0,768), k = cols [768,1536) of qkv
    gemm_bf16<true, false><<<dim3(SS / 256, SS / 128, BB), blk, SMEM_NT>>>(
        qkv_h, qkv_l, qkv_h + EE, qkv_l + EE, nullptr, sbuf, nullptr, nullptr,
        nullptr, EE, NQKV, NQKV, SS,
        (long long)SS * NQKV, (long long)SS * NQKV, (long long)SS * SS);

    // Softmax -> single fp16 P (trimmed)
    softmax_causal<<<dim3(SS, BB), blk>>>(sbuf, amask, p16);

    // PV: fp16, 1 MMA per k-step
    gemm_pv<<<dim3(EE / 256, SS / 128, BB), blk, SMEM_PV>>>(p16, v16, abuf);

    // Fused MLP head -> out [B*S, 2]
    mlp_kernel<<<MM / 4, blk>>>(abuf, w1t, b1, W2, b2, out);
}

// round 17
// speedup vs baseline: 1.2475x; 1.0907x over previous
#include <cuda_runtime.h>
#include <cstdint>

// Problem constants
#define BB 32
#define SS 1024
#define EE 768
#define HH 64
#define LL 2
#define MM (BB * SS)

typedef unsigned short u16;

// ---------------------------------------------------------------------------
// Scratch (static device allocations)
// ---------------------------------------------------------------------------
__device__ u16  g_hid_h[(size_t)MM * EE], g_hid_l[(size_t)MM * EE];
__device__ u16  g_wqt_h[EE * EE], g_wqt_l[EE * EE];     // Wq^T, split bf16
__device__ u16  g_wk_h[EE * EE],  g_wk_l[EE * EE];      // Wk as-is [e,g]
__device__ u16  g_wv_h[EE * EE],  g_wv_l[EE * EE];      // Wv as-is [e,f]
__device__ u16  g_G_h[EE * EE],   g_G_l[EE * EE];       // G = Wq^T Wk [f,g]
__device__ u16  g_t_h[(size_t)MM * EE], g_t_l[(size_t)MM * EE];  // T = hid·G
__device__ u16  g_v16[(size_t)MM * EE];                 // V single fp16 [s][e]
__device__ u16  g_p16[(size_t)BB * SS * SS];            // P single fp16
__device__ float g_s[(size_t)BB * SS * SS];
__device__ float g_a[(size_t)MM * EE];
__device__ float g_w1t[EE * HH];
__device__ float g_cvec[EE];                            // Wk^T · bq
__device__ float g_vvec[MM];                            // hid · cvec

// ---------------------------------------------------------------------------
// helpers
// ---------------------------------------------------------------------------
__device__ __forceinline__ uint32_t smem_u32(const void* p) {
    return (uint32_t)__cvta_generic_to_shared(p);
}
__device__ __forceinline__ void ldm4(uint32_t* r, uint32_t addr) {
    asm volatile("ldmatrix.sync.aligned.m8n8.x4.shared.b16 {%0,%1,%2,%3}, [%4];"
                 : "=r"(r[0]), "=r"(r[1]), "=r"(r[2]), "=r"(r[3]) : "r"(addr));
}
__device__ __forceinline__ void ldm4t(uint32_t* r, uint32_t addr) {
    asm volatile("ldmatrix.sync.aligned.m8n8.x4.trans.shared.b16 {%0,%1,%2,%3}, [%4];"
                 : "=r"(r[0]), "=r"(r[1]), "=r"(r[2]), "=r"(r[3]) : "r"(addr));
}
__device__ __forceinline__ void mma16816(float* d, const uint32_t* a,
                                         uint32_t b0, uint32_t b1) {
    asm volatile(
        "mma.sync.aligned.m16n8k16.row.col.f32.bf16.bf16.f32 "
        "{%0,%1,%2,%3},{%4,%5,%6,%7},{%8,%9},{%0,%1,%2,%3};"
        : "+f"(d[0]), "+f"(d[1]), "+f"(d[2]), "+f"(d[3])
        : "r"(a[0]), "r"(a[1]), "r"(a[2]), "r"(a[3]), "r"(b0), "r"(b1));
}
__device__ __forceinline__ void mma16816h(float* d, const uint32_t* a,
                                          uint32_t b0, uint32_t b1) {
    asm volatile(
        "mma.sync.aligned.m16n8k16.row.col.f32.f16.f16.f32 "
        "{%0,%1,%2,%3},{%4,%5,%6,%7},{%8,%9},{%0,%1,%2,%3};"
        : "+f"(d[0]), "+f"(d[1]), "+f"(d[2]), "+f"(d[3])
        : "r"(a[0]), "r"(a[1]), "r"(a[2]), "r"(a[3]), "r"(b0), "r"(b1));
}

// ---- bf16 split ----
__device__ __forceinline__ uint32_t bfr(float x) {
    uint32_t u = __float_as_uint(x);
    return (u + 0x7fffu + ((u >> 16) & 1u)) >> 16;
}
__device__ __forceinline__ float bff(uint32_t h) { return __uint_as_float(h << 16); }
__device__ __forceinline__ uint32_t pack2(float a, float b) {   // lo=a, hi=b
    uint32_t r;
    asm("cvt.rn.bf16x2.f32 %0, %1, %2;" : "=r"(r) : "f"(b), "f"(a));
    return r;
}
__device__ __forceinline__ void cvt_hl(float a, float b, uint32_t& h, uint32_t& l) {
    h = pack2(a, b);
    float ha = __uint_as_float(h << 16);
    float hb = __uint_as_float(h & 0xffff0000u);
    l = pack2(a - ha, b - hb);
}
// ---- fp16 pack ----
__device__ __forceinline__ uint32_t pack2f(float a, float b) {
    uint32_t r;
    asm("cvt.rn.f16x2.f32 %0, %1, %2;" : "=r"(r) : "f"(b), "f"(a));
    return r;
}

// ---------------------------------------------------------------------------
// One-time f32 -> (hi, lo) bf16 split, vectorized (hidden)
// ---------------------------------------------------------------------------
__global__ void split_f32(const float4* __restrict__ x, uint2* __restrict__ h,
                          uint2* __restrict__ l, int n4)
{
    for (int i = blockIdx.x * blockDim.x + threadIdx.x; i < n4;
         i += gridDim.x * blockDim.x) {
        float4 f = x[i];
        uint2 hh, ll;
        cvt_hl(f.x, f.y, hh.x, ll.x);
        cvt_hl(f.z, f.w, hh.y, ll.y);
        h[i] = hh; l[i] = ll;
    }
}

// ---------------------------------------------------------------------------
// Weight prep: split Wk, Wv in place; split-transpose Wq; cvec = Wk^T·bq;
// transpose W1.
// ---------------------------------------------------------------------------
__global__ void prep_weights(
    const float4* __restrict__ Wq4, const float4* __restrict__ Wk4,
    const float4* __restrict__ Wv4, const float* __restrict__ Wq,
    const float* __restrict__ Wk, const float* __restrict__ bq,
    const float* __restrict__ W1,
    uint2* __restrict__ wkh, uint2* __restrict__ wkl,
    uint2* __restrict__ wvh, uint2* __restrict__ wvl,
    u16* __restrict__ wqth, u16* __restrict__ wqtl,
    float* __restrict__ cvec, float* __restrict__ w1t)
{
    const int stride = gridDim.x * blockDim.x;
    const int gid = blockIdx.x * blockDim.x + threadIdx.x;
    const int W4 = EE * EE / 4;
    for (int i = gid; i < W4; i += stride) {
        float4 f = Wk4[i];
        uint2 hh, ll;
        cvt_hl(f.x, f.y, hh.x, ll.x);
        cvt_hl(f.z, f.w, hh.y, ll.y);
        wkh[i] = hh; wkl[i] = ll;
        f = Wv4[i];
        cvt_hl(f.x, f.y, hh.x, ll.x);
        cvt_hl(f.z, f.w, hh.y, ll.y);
        wvh[i] = hh; wvl[i] = ll;
    }
    // Wq split-transposed: wqt[f,e] = Wq[e,f]
    for (int i = gid; i < EE * EE; i += stride) {
        const int e = i / EE, f = i - e * EE;
        const float x = Wq[i];
        const uint32_t h = bfr(x);
        const uint32_t l = bfr(x - bff(h));
        wqth[f * EE + e] = (u16)h;
        wqtl[f * EE + e] = (u16)l;
    }
    // cvec[g] = sum_e Wk[e,g] * bq[e]
    for (int g = gid; g < EE; g += stride) {
        float s = 0.f;
        for (int e = 0; e < EE; e++) s += Wk[e * EE + g] * bq[e];
        cvec[g] = s;
    }
    for (int i = gid; i < HH * EE; i += stride)
        w1t[(i % EE) * HH + (i / EE)] = W1[i];
}

// ---------------------------------------------------------------------------
// vvec[s] = hid[s,:] · cvec  (warp per row)
// ---------------------------------------------------------------------------
__global__ __launch_bounds__(256) void gemv_v(
    const float* __restrict__ hid, const float* __restrict__ cvec,
    float* __restrict__ vvec)
{
    const int row = blockIdx.x * 8 + (threadIdx.x >> 5);
    const int lane = threadIdx.x & 31;
    float s = 0.f;
    const float* hr = hid + (size_t)row * EE;
    for (int f = lane; f < EE; f += 32) s += hr[f] * cvec[f];
#pragma unroll
    for (int o = 16; o > 0; o >>= 1) s += __shfl_xor_sync(0xffffffffu, s, o);
    if (lane == 0) vvec[row] = s;
}

// ---------------------------------------------------------------------------
// Split-bf16 tensor-core GEMM: C[m,n] = sum_k A[m,k]*B(k,n) + bias[n]
// 256 threads, 8 warps (2x4), warp 64x64, register staging, double-buffered,
// term-major 3-MMA nest, causal skip + epilogue store-skip.
//   BTRANS: B in [k,n] layout (ldm4t)      — used by G and T GEMMs
//   OUTMODE: 0 = f32 (+causal store skip), 1 = bf16 hi/lo pair,
//            2 = fp16 single (into Ch)
// ---------------------------------------------------------------------------
#define RSA 40     // smem row stride, u16
#define RSBT 264   // trans-B smem row stride, u16

template<bool BTRANS, bool CAUSAL, int OUTMODE>
__global__ __launch_bounds__(256, 1) void gemm_bf16(
    const u16* __restrict__ Agh, const u16* __restrict__ Agl,
    const u16* __restrict__ Bgh, const u16* __restrict__ Bgl,
    const float* __restrict__ bias,
    float* __restrict__ Cf, u16* __restrict__ Ch, u16* __restrict__ Cl,
    int K, int lda, int ldb, int ldc,
    long long sA, long long sB, long long sC)
{
    const int n0 = blockIdx.x * 256;
    const int m0 = blockIdx.y * 128;
    if (CAUSAL && n0 >= m0 + 128) return;

    Agh += (long long)blockIdx.z * sA; Agl += (long long)blockIdx.z * sA;
    Bgh += (long long)blockIdx.z * sB; Bgl += (long long)blockIdx.z * sB;
    if (OUTMODE == 0) Cf += (long long)blockIdx.z * sC;

    const int ktiles = K / 32;

    constexpr int ASZ = 128 * RSA;
    constexpr int BSZ = BTRANS ? 32 * RSBT : 256 * RSA;
    constexpr int OAh = 0, OAl = ASZ, OBh = 2 * ASZ, OBl = 2 * ASZ + BSZ;
    constexpr int STGU = 2 * ASZ + 2 * BSZ;

    extern __shared__ __align__(16) u16 sm[];

    const int tid  = threadIdx.x;
    const int lane = tid & 31;
    const int wid  = tid >> 5;
    const int wm   = wid >> 2;   // 0..1
    const int wn   = wid & 3;    // 0..3

    const int wmBase = m0 + wm * 64;
    const int wnBase = n0 + wn * 64;

    uint4 rah[2], ral[2], rbh[4], rbl[4];

    auto loadT = [&](int k0) {
#pragma unroll
        for (int t = 0; t < 2; t++) {
            const int v = tid + t * 256;
            const size_t g = (size_t)(m0 + (v >> 2)) * lda + k0 + (v & 3) * 8;
            rah[t] = *reinterpret_cast<const uint4*>(Agh + g);
            ral[t] = *reinterpret_cast<const uint4*>(Agl + g);
        }
        if (!BTRANS) {
#pragma unroll
            for (int t = 0; t < 4; t++) {
                const int v = tid + t * 256;
                const size_t g = (size_t)(n0 + (v >> 2)) * ldb + k0 + (v & 3) * 8;
                rbh[t] = *reinterpret_cast<const uint4*>(Bgh + g);
                rbl[t] = *reinterpret_cast<const uint4*>(Bgl + g);
            }
        } else {
#pragma unroll
            for (int t = 0; t < 4; t++) {
                const int v = tid + t * 256;
                const size_t g = (size_t)(k0 + (v >> 5)) * ldb + n0 + (v & 31) * 8;
                rbh[t] = *reinterpret_cast<const uint4*>(Bgh + g);
                rbl[t] = *reinterpret_cast<const uint4*>(Bgl + g);
            }
        }
    };

    auto storeT = [&](int s) {
        u16* base = sm + s * STGU;
#pragma unroll
        for (int t = 0; t < 2; t++) {
            const int v = tid + t * 256;
            const int off = (v >> 2) * RSA + (v & 3) * 8;
            *reinterpret_cast<uint4*>(base + OAh + off) = rah[t];
            *reinterpret_cast<uint4*>(base + OAl + off) = ral[t];
        }
        if (!BTRANS) {
#pragma unroll
            for (int t = 0; t < 4; t++) {
                const int v = tid + t * 256;
                const int off = (v >> 2) * RSA + (v & 3) * 8;
                *reinterpret_cast<uint4*>(base + OBh + off) = rbh[t];
                *reinterpret_cast<uint4*>(base + OBl + off) = rbl[t];
            }
        } else {
#pragma unroll
            for (int t = 0; t < 4; t++) {
                const int v = tid + t * 256;
                const int off = (v >> 5) * RSBT + (v & 31) * 8;
                *reinterpret_cast<uint4*>(base + OBh + off) = rbh[t];
                *reinterpret_cast<uint4*>(base + OBl + off) = rbl[t];
            }
        }
    };

    const uint32_t smB = smem_u32(sm);
    const int aRow  = wm * 64 + (lane & 7) + ((lane >> 3) & 1) * 8;
    const int aColS = ((lane >> 4) & 1) * 8;
    const int bRow  = wn * 64 + (lane & 7) + ((lane >> 4) & 1) * 8;
    const int bColS = ((lane >> 3) & 1) * 8;
    const int btK = (lane & 7) + ((lane >> 3) & 1) * 8;
    const int btN = wn * 64 + ((lane >> 4) & 1) * 8;

    float acc[4][8][4];
#pragma unroll
    for (int i = 0; i < 4; i++)
#pragma unroll
        for (int j = 0; j < 8; j++)
#pragma unroll
            for (int c = 0; c < 4; c++) acc[i][j][c] = 0.f;

    loadT(0);
    storeT(0);
    __syncthreads();

    int s = 0;
    for (int kt = 0; kt < ktiles; kt++) {
        const bool more = (kt + 1 < ktiles);
        if (more) loadT((kt + 1) * 32);

        const uint32_t stB = smB + (uint32_t)s * (STGU * 2);
#pragma unroll
        for (int ks = 0; ks < 2; ks++) {
            uint32_t ah[4][4], al[4][4];
#pragma unroll
            for (int mt = 0; mt < 4; mt++) {
                uint32_t off = (uint32_t)(((aRow + mt * 16) * RSA) + ks * 16 + aColS) * 2;
                ldm4(ah[mt], stB + OAh * 2 + off);
                ldm4(al[mt], stB + OAl * 2 + off);
            }
#pragma unroll
            for (int np = 0; np < 4; np++) {
                const bool np_active = !CAUSAL || (wnBase + np * 16 <= wmBase + 63);
                if (!np_active) continue;
                uint32_t bh[4], bl[4];
                if (!BTRANS) {
                    uint32_t off = (uint32_t)(((bRow + np * 16) * RSA) + ks * 16 + bColS) * 2;
                    ldm4(bh, stB + OBh * 2 + off);
                    ldm4(bl, stB + OBl * 2 + off);
                } else {
                    uint32_t off = (uint32_t)((ks * 16 + btK) * RSBT + btN + np * 16) * 2;
                    ldm4t(bh, stB + OBh * 2 + off);
                    ldm4t(bl, stB + OBl * 2 + off);
                }
                // term-major: break accumulator RAW chains
#pragma unroll
                for (int h = 0; h < 2; h++)
#pragma unroll
                    for (int mt = 0; mt < 4; mt++)
                        if (!CAUSAL || (wnBase + (np * 2 + h) * 8 <= wmBase + mt * 16 + 15))
                            mma16816(acc[mt][np * 2 + h], ah[mt], bh[2 * h], bh[2 * h + 1]);
#pragma unroll
                for (int h = 0; h < 2; h++)
#pragma unroll
                    for (int mt = 0; mt < 4; mt++)
                        if (!CAUSAL || (wnBase + (np * 2 + h) * 8 <= wmBase + mt * 16 + 15))
                            mma16816(acc[mt][np * 2 + h], ah[mt], bl[2 * h], bl[2 * h + 1]);
#pragma unroll
                for (int h = 0; h < 2; h++)
#pragma unroll
                    for (int mt = 0; mt < 4; mt++)
                        if (!CAUSAL || (wnBase + (np * 2 + h) * 8 <= wmBase + mt * 16 + 15))
                            mma16816(acc[mt][np * 2 + h], al[mt], bh[2 * h], bh[2 * h + 1]);
            }
            if (ks == 0 && more) storeT(s ^ 1);
        }
        __syncthreads();
        s ^= 1;
    }

    // epilogue
#pragma unroll
    for (int mt = 0; mt < 4; mt++) {
        const int m = m0 + wm * 64 + mt * 16 + (lane >> 2);
#pragma unroll
        for (int nt = 0; nt < 8; nt++) {
            const int n = n0 + wn * 64 + nt * 8 + (lane & 3) * 2;
            float b0 = 0.f, b1 = 0.f;
            if (bias) { b0 = bias[n]; b1 = bias[n + 1]; }
            const float x0 = acc[mt][nt][0] + b0, x1 = acc[mt][nt][1] + b1;
            const float x2 = acc[mt][nt][2] + b0, x3 = acc[mt][nt][3] + b1;
            if (OUTMODE == 0) {
                float2 v0 = {x0, x1}, v1 = {x2, x3};
                if (!CAUSAL || n <= m)
                    *reinterpret_cast<float2*>(&Cf[(size_t)m * ldc + n]) = v0;
                if (!CAUSAL || n <= m + 8)
                    *reinterpret_cast<float2*>(&Cf[(size_t)(m + 8) * ldc + n]) = v1;
            } else if (OUTMODE == 1) {
                uint32_t h, l;
                cvt_hl(x0, x1, h, l);
                *reinterpret_cast<uint32_t*>(&Ch[(size_t)m * ldc + n]) = h;
                *reinterpret_cast<uint32_t*>(&Cl[(size_t)m * ldc + n]) = l;
                cvt_hl(x2, x3, h, l);
                *reinterpret_cast<uint32_t*>(&Ch[(size_t)(m + 8) * ldc + n]) = h;
                *reinterpret_cast<uint32_t*>(&Cl[(size_t)(m + 8) * ldc + n]) = l;
            } else {
                *reinterpret_cast<uint32_t*>(&Ch[(size_t)m * ldc + n]) = pack2f(x0, x1);
                *reinterpret_cast<uint32_t*>(&Ch[(size_t)(m + 8) * ldc + n]) = pack2f(x2, x3);
            }
        }
    }
}

// ---------------------------------------------------------------------------
// PV GEMM (fp16, 1 MMA per k-step): a = P @ V (unchanged from R15)
// ---------------------------------------------------------------------------
__global__ __launch_bounds__(256, 1) void gemm_pv(
    const u16* __restrict__ Pg, const u16* __restrict__ Vg,
    float* __restrict__ Cf)
{
    const int n0 = blockIdx.x * 256;
    const int m0 = blockIdx.y * 128;

    Pg += (long long)blockIdx.z * SS * SS;
    Vg += (long long)blockIdx.z * SS * EE;
    Cf += (long long)blockIdx.z * SS * EE;

    const int ktiles = (m0 + 128) / 32;

    constexpr int ASZ = 128 * RSA;
    constexpr int BSZ = 32 * RSBT;
    constexpr int OAp = 0, OBv = ASZ;
    constexpr int STGU = ASZ + BSZ;

    extern __shared__ __align__(16) u16 sm[];
    const uint32_t smB = smem_u32(sm);

    const int tid  = threadIdx.x;
    const int lane = tid & 31;
    const int wid  = tid >> 5;
    const int wm   = wid >> 2;
    const int wn   = wid & 3;

    const int wmBase = m0 + wm * 64;

    uint4 rap[2], rbv[4];

    auto loadT = [&](int k0) {
#pragma unroll
        for (int t = 0; t < 2; t++) {
            const int v = tid + t * 256;
            rap[t] = *reinterpret_cast<const uint4*>(
                Pg + (size_t)(m0 + (v >> 2)) * SS + k0 + (v & 3) * 8);
        }
#pragma unroll
        for (int t = 0; t < 4; t++) {
            const int u = tid + t * 256;
            rbv[t] = *reinterpret_cast<const uint4*>(
                Vg + (size_t)(k0 + (u >> 5)) * EE + n0 + (u & 31) * 8);
        }
    };

    auto storeT = [&](int s) {
        u16* base = sm + s * STGU;
#pragma unroll
        for (int t = 0; t < 2; t++) {
            const int v = tid + t * 256;
            const int off = (v >> 2) * RSA + (v & 3) * 8;
            *reinterpret_cast<uint4*>(base + OAp + off) = rap[t];
        }
#pragma unroll
        for (int t = 0; t < 4; t++) {
            const int u = tid + t * 256;
            const int off = (u >> 5) * RSBT + (u & 31) * 8;
            *reinterpret_cast<uint4*>(base + OBv + off) = rbv[t];
        }
    };

    const int aRow  = wm * 64 + (lane & 7) + ((lane >> 3) & 1) * 8;
    const int aColS = ((lane >> 4) & 1) * 8;
    const int btK = (lane & 7) + ((lane >> 3) & 1) * 8;
    const int btN = wn * 64 + ((lane >> 4) & 1) * 8;

    float acc[4][8][4];
#pragma unroll
    for (int i = 0; i < 4; i++)
#pragma unroll
        for (int j = 0; j < 8; j++)
#pragma unroll
            for (int c = 0; c < 4; c++) acc[i][j][c] = 0.f;

    loadT(0);
    storeT(0);
    __syncthreads();

    int s = 0;
    for (int kt = 0; kt < ktiles; kt++) {
        const bool more = (kt + 1 < ktiles);
        if (more) loadT((kt + 1) * 32);

        const uint32_t stB = smB + (uint32_t)s * (STGU * 2);
#pragma unroll
        for (int ks = 0; ks < 2; ks++) {
            const bool wactive = (kt * 32 + ks * 16 <= wmBase + 63);
            if (wactive) {
                uint32_t ap[4][4];
#pragma unroll
                for (int mt = 0; mt < 4; mt++) {
                    uint32_t off = (uint32_t)(((aRow + mt * 16) * RSA) + ks * 16 + aColS) * 2;
                    ldm4(ap[mt], stB + OAp * 2 + off);
                }
#pragma unroll
                for (int np = 0; np < 4; np++) {
                    uint32_t bv[4];
                    uint32_t off = (uint32_t)((ks * 16 + btK) * RSBT + btN + np * 16) * 2;
                    ldm4t(bv, stB + OBv * 2 + off);
#pragma unroll
                    for (int h = 0; h < 2; h++)
#pragma unroll
                        for (int mt = 0; mt < 4; mt++)
                            mma16816h(acc[mt][np * 2 + h], ap[mt], bv[2 * h], bv[2 * h + 1]);
                }
            }
            if (ks == 0 && more) storeT(s ^ 1);
        }
        __syncthreads();
        s ^= 1;
    }

#pragma unroll
    for (int mt = 0; mt < 4; mt++) {
        const int m = m0 + wm * 64 + mt * 16 + (lane >> 2);
#pragma unroll
        for (int nt = 0; nt < 8; nt++) {
            const int n = n0 + wn * 64 + nt * 8 + (lane & 3) * 2;
            float2 v0 = {acc[mt][nt][0], acc[mt][nt][1]};
            float2 v1 = {acc[mt][nt][2], acc[mt][nt][3]};
            *reinterpret_cast<float2*>(&Cf[(size_t)m * EE + n]) = v0;
            *reinterpret_cast<float2*>(&Cf[(size_t)(m + 8) * EE + n]) = v1;
        }
    }
}

#define SMEM_NT ((2 * (2 * 128 * RSA + 2 * 256 * RSA)) * 2)
#define SMEM_BT ((2 * (2 * 128 * RSA + 2 * 32 * RSBT)) * 2)
#define SMEM_PV ((2 * (128 * RSA + 32 * RSBT)) * 2)

// ---------------------------------------------------------------------------
// Row-wise causal softmax -> single fp16 P; adds per-column bias v_j
// (the surviving bias term of the folded QK algebra). Trimmed to round128.
// ---------------------------------------------------------------------------
__global__ __launch_bounds__(256) void softmax_causal(
    const float* __restrict__ Smat, const float* __restrict__ amask,
    const float* __restrict__ vvec, u16* __restrict__ Ph)
{
    const int i = blockIdx.x;
    const int b = blockIdx.y;
    const int jmax = ((i >> 7) + 1) << 7;
    const size_t rbase = ((size_t)b * SS + i) * SS;
    const float* row = Smat + rbase;
    const float* am = amask + (size_t)b * SS;
    const float* vv = vvec + (size_t)b * SS;
    const int tid = threadIdx.x;

    float vals[4];
    int cnt = 0;
    float mx = -1e30f;
    for (int j = tid * 2; j < jmax; j += 512) {
        float s0 = -10000.0f, s1 = -10000.0f;
        if (j <= i) {
            float2 f = *reinterpret_cast<const float2*>(&row[j]);
            s0 = f.x + vv[j] + (1.0f - am[j]) * -10000.0f;
            if (j + 1 <= i) s1 = f.y + vv[j + 1] + (1.0f - am[j + 1]) * -10000.0f;
        }
        vals[cnt] = s0; vals[cnt + 1] = s1; cnt += 2;
        mx = fmaxf(mx, fmaxf(s0, s1));
    }

    __shared__ float red[8];
#pragma unroll
    for (int o = 16; o > 0; o >>= 1) mx = fmaxf(mx, __shfl_xor_sync(0xffffffffu, mx, o));
    if ((tid & 31) == 0) red[tid >> 5] = mx;
    __syncthreads();
    mx = red[0];
#pragma unroll
    for (int w = 1; w < 8; w++) mx = fmaxf(mx, red[w]);

    float sum = 0.f;
    for (int c = 0; c < cnt; c++) {
        vals[c] = __expf(vals[c] - mx);
        sum += vals[c];
    }
#pragma unroll
    for (int o = 16; o > 0; o >>= 1) sum += __shfl_xor_sync(0xffffffffu, sum, o);
    __syncthreads();
    if ((tid & 31) == 0) red[tid >> 5] = sum;
    __syncthreads();
    sum = 0.f;
#pragma unroll
    for (int w = 0; w < 8; w++) sum += red[w];

    const float inv = 1.0f / sum;
    int c = 0;
    for (int j = tid * 2; j < jmax; j += 512) {
        *reinterpret_cast<uint32_t*>(&Ph[rbase + j]) =
            pack2f(vals[c] * inv, vals[c + 1] * inv);
        c += 2;
    }
}

// ---------------------------------------------------------------------------
// Fused MLP head: out = relu(X @ W1^T + b1) @ W2^T + b2
// ---------------------------------------------------------------------------
__global__ __launch_bounds__(256) void mlp_kernel(
    const float* __restrict__ X, const float* __restrict__ W1t,
    const float* __restrict__ b1, const float* __restrict__ W2,
    const float* __restrict__ b2, float* __restrict__ out)
{
    __shared__ float xs[4][EE];
    __shared__ float hs[4][HH];
    const int row0 = blockIdx.x * 4;
    const int tid = threadIdx.x;

    for (int v = tid; v < 4 * EE; v += 256)
        xs[v / EE][v % EE] = X[(size_t)(row0 + v / EE) * EE + (v % EE)];
    __syncthreads();

    const int c  = tid & 63;
    const int rr = tid >> 6;
    float a0 = 0.f, a1 = 0.f, a2 = 0.f, a3 = 0.f;
#pragma unroll 4
    for (int e = 0; e < EE; e += 4) {
        a0 += xs[rr][e + 0] * W1t[(e + 0) * HH + c];
        a1 += xs[rr][e + 1] * W1t[(e + 1) * HH + c];
        a2 += xs[rr][e + 2] * W1t[(e + 2) * HH + c];
        a3 += xs[rr][e + 3] * W1t[(e + 3) * HH + c];
    }
    float acc = b1[c] + ((a0 + a1) + (a2 + a3));
    hs[rr][c] = fmaxf(acc, 0.f);
    __syncthreads();

    if (tid < 4 * LL) {
        int r2 = tid >> 1;
        int l  = tid & 1;
        float s = b2[l];
#pragma unroll
        for (int h = 0; h < HH; h++) s += hs[r2][h] * W2[l * HH + h];
        out[(size_t)(row0 + r2) * LL + l] = s;
    }
}

// ---------------------------------------------------------------------------
extern "C" void kernel_launch(void* const* d_in, const int* in_sizes, int n_in,
                              void* d_out, int out_size)
{
    const float* hidden = (const float*)d_in[0];
    const float* amask  = (const float*)d_in[1];
    const float* Wk = (const float*)d_in[2];
    const float* bk = (const float*)d_in[3];   // annihilated by softmax shift
    const float* Wq = (const float*)d_in[4];
    const float* bq = (const float*)d_in[5];
    const float* Wv = (const float*)d_in[6];
    const float* bv = (const float*)d_in[7];
    const float* W1 = (const float*)d_in[8];
    const float* b1 = (const float*)d_in[9];
    const float* W2 = (const float*)d_in[10];
    const float* b2 = (const float*)d_in[11];
    float* out = (float*)d_out;
    (void)bk;

    u16 *hid_h, *hid_l, *wqt_h, *wqt_l, *wk_h, *wk_l, *wv_h, *wv_l;
    u16 *G_h, *G_l, *t_h, *t_l, *v16, *p16;
    float *sbuf, *abuf, *w1t, *cvec, *vvec;
    cudaGetSymbolAddress((void**)&hid_h, g_hid_h); cudaGetSymbolAddress((void**)&hid_l, g_hid_l);
    cudaGetSymbolAddress((void**)&wqt_h, g_wqt_h); cudaGetSymbolAddress((void**)&wqt_l, g_wqt_l);
    cudaGetSymbolAddress((void**)&wk_h, g_wk_h);   cudaGetSymbolAddress((void**)&wk_l, g_wk_l);
    cudaGetSymbolAddress((void**)&wv_h, g_wv_h);   cudaGetSymbolAddress((void**)&wv_l, g_wv_l);
    cudaGetSymbolAddress((void**)&G_h, g_G_h);     cudaGetSymbolAddress((void**)&G_l, g_G_l);
    cudaGetSymbolAddress((void**)&t_h, g_t_h);     cudaGetSymbolAddress((void**)&t_l, g_t_l);
    cudaGetSymbolAddress((void**)&v16, g_v16);     cudaGetSymbolAddress((void**)&p16, g_p16);
    cudaGetSymbolAddress((void**)&sbuf, g_s);
    cudaGetSymbolAddress((void**)&abuf, g_a);
    cudaGetSymbolAddress((void**)&w1t, g_w1t);
    cudaGetSymbolAddress((void**)&cvec, g_cvec);
    cudaGetSymbolAddress((void**)&vvec, g_vvec);

    cudaFuncSetAttribute((const void*)gemm_bf16<false, false, 2>,
                         cudaFuncAttributeMaxDynamicSharedMemorySize, SMEM_NT);
    cudaFuncSetAttribute((const void*)gemm_bf16<true, false, 1>,
                         cudaFuncAttributeMaxDynamicSharedMemorySize, SMEM_BT);
    cudaFuncSetAttribute((const void*)gemm_bf16<false, true, 0>,
                         cudaFuncAttributeMaxDynamicSharedMemorySize, SMEM_NT);
    cudaFuncSetAttribute((const void*)gemm_pv,
                         cudaFuncAttributeMaxDynamicSharedMemorySize, SMEM_PV);

    const dim3 blk(256);

    // Prep
    split_f32<<<2368, blk>>>((const float4*)hidden, (uint2*)hid_h, (uint2*)hid_l,
                             MM * EE / 4);
    prep_weights<<<1184, blk>>>((const float4*)Wq, (const float4*)Wk,
                                (const float4*)Wv, Wq, Wk, bq, W1,
                                (uint2*)wk_h, (uint2*)wk_l,
                                (uint2*)wv_h, (uint2*)wv_l,
                                wqt_h, wqt_l, cvec, w1t);

    // G = Wq^T @ Wk  [f,g]  (A = Wq^T k-major, B = Wk in [k,n] -> BTRANS)
    gemm_bf16<true, false, 1><<<dim3(EE / 256, EE / 128, 1), blk, SMEM_BT>>>(
        wqt_h, wqt_l, wk_h, wk_l, nullptr, nullptr, G_h, G_l,
        EE, EE, EE, EE, 0, 0, 0);

    // V = hid @ Wv^T + bv -> single fp16
    gemm_bf16<false, false, 2><<<dim3(EE / 256, MM / 128, 1), blk, SMEM_NT>>>(
        hid_h, hid_l, wv_h, wv_l, bv, nullptr, v16, nullptr,
        EE, EE, EE, EE, 0, 0, 0);

    // T = hid @ G  [i,g]  (B = G in [k,n] -> BTRANS) -> bf16 hi/lo
    gemm_bf16<true, false, 1><<<dim3(EE / 256, MM / 128, 1), blk, SMEM_BT>>>(
        hid_h, hid_l, G_h, G_l, nullptr, nullptr, t_h, t_l,
        EE, EE, EE, EE, 0, 0, 0);

    // vvec = hid · (Wk^T bq)
    gemv_v<<<MM / 8, blk>>>(hidden, cvec, vvec);

    // scores = T @ hid^T (causal) -> f32
    gemm_bf16<false, true, 0><<<dim3(SS / 256, SS / 128, BB), blk, SMEM_NT>>>(
        t_h, t_l, hid_h, hid_l, nullptr, sbuf, nullptr, nullptr,
        EE, EE, EE, SS,
        (long long)SS * EE, (long long)SS * EE, (long long)SS * SS);

    // Softmax (adds v_j) -> single fp16 P
    softmax_causal<<<dim3(SS, BB), blk>>>(sbuf, amask, vvec, p16);

    // PV: fp16, 1 MMA per k-step
    gemm_pv<<<dim3(EE / 256, SS / 128, BB), blk, SMEM_PV>>>(p16, v16, abuf);

    // Fused MLP head -> out [B*S, 2]
    mlp_kernel<<<MM / 4, blk>>>(abuf, w1t, b1, W2, b2, out);
}